// round 1
// baseline (speedup 1.0000x reference)
#include <cuda_runtime.h>
#include <math.h>

// Problem constants
#define B_   4
#define T_   1024
#define C_   768
#define H_   12
#define D_   64
#define FA_  (3*C_)          // 2304
#define BHT_ (B_*H_*T_)      // 49152
#define ROWS_ (B_*T_)        // 4096
#define EPSY (1.0f/137.0f)

// ---------------- scratch (device globals: allocation-free) ----------------
__device__ float g_q [B_*H_*T_*D_];
__device__ float g_k [B_*H_*T_*D_];
__device__ float g_v [B_*H_*T_*D_];
__device__ float g_S [(size_t)B_*H_*T_*T_];   // 201 MB score matrix
__device__ float g_ao[B_*T_*C_];              // attention output [B,T,C]
__device__ float g_xn [ROWS_];                // ||x_row||^2
__device__ float g_aon[ROWS_];                // ||ao_row||^2
__device__ float g_wna[FA_];                  // ||W_attn col||^2
__device__ float g_wnp[C_];                   // ||W_proj col||^2
__device__ float g_qn [BHT_];
__device__ float g_kn [BHT_];

// ---------------- norm kernels ----------------
__global__ void rownorm_x(const float* __restrict__ X) {
    __shared__ float sh[256];
    int r = blockIdx.x;
    const float* p = X + (size_t)r * C_;
    float s = 0.f;
    for (int c = threadIdx.x; c < C_; c += 256) { float v = p[c]; s += v*v; }
    sh[threadIdx.x] = s; __syncthreads();
    for (int o = 128; o; o >>= 1) { if (threadIdx.x < o) sh[threadIdx.x] += sh[threadIdx.x + o]; __syncthreads(); }
    if (threadIdx.x == 0) g_xn[r] = sh[0];
}

__global__ void rownorm_ao() {
    __shared__ float sh[256];
    int r = blockIdx.x;
    const float* p = g_ao + (size_t)r * C_;
    float s = 0.f;
    for (int c = threadIdx.x; c < C_; c += 256) { float v = p[c]; s += v*v; }
    sh[threadIdx.x] = s; __syncthreads();
    for (int o = 128; o; o >>= 1) { if (threadIdx.x < o) sh[threadIdx.x] += sh[threadIdx.x + o]; __syncthreads(); }
    if (threadIdx.x == 0) g_aon[r] = sh[0];
}

__global__ void colnorm_attn(const float* __restrict__ W) {
    int c = blockIdx.x * blockDim.x + threadIdx.x;
    if (c >= FA_) return;
    float s = 0.f;
    for (int r = 0; r < C_; r++) { float v = W[(size_t)r * FA_ + c]; s += v*v; }
    g_wna[c] = s;
}

__global__ void colnorm_proj(const float* __restrict__ W) {
    int c = blockIdx.x * blockDim.x + threadIdx.x;
    if (c >= C_) return;
    float s = 0.f;
    for (int r = 0; r < C_; r++) { float v = W[(size_t)r * C_ + c]; s += v*v; }
    g_wnp[c] = s;
}

// q/k row norms: one warp per 64-wide row, both tensors in one launch
__global__ void qknorm_kernel() {
    int gw   = (blockIdx.x * blockDim.x + threadIdx.x) >> 5;
    int lane = threadIdx.x & 31;
    if (gw >= 2 * BHT_) return;
    bool isQ = gw < BHT_;
    int r = isQ ? gw : gw - BHT_;
    const float* p = (isQ ? g_q : g_k) + (size_t)r * D_;
    float a = p[lane], b = p[lane + 32];
    float s = a*a + b*b;
    #pragma unroll
    for (int o = 16; o; o >>= 1) s += __shfl_xor_sync(0xffffffffu, s, o);
    if (lane == 0) (isQ ? g_qn : g_kn)[r] = s;
}

// ---------------- QKV yat_dense GEMM: [4096,768] x [768,2304] ----------------
__global__ __launch_bounds__(256) void qkv_kernel(const float* __restrict__ X,
                                                  const float* __restrict__ W,
                                                  const float* __restrict__ bias,
                                                  const float* __restrict__ alpha) {
    __shared__ float As[16][64];
    __shared__ float Bs[16][64];
    const int tid = threadIdx.x;
    const int tx = tid & 15, ty = tid >> 4;
    const int rowBase = blockIdx.y * 64;
    const int colBase = blockIdx.x * 64;
    const int aRow = tid >> 2, aCol = (tid & 3) * 4;
    const int bRow = tid >> 4, bCol = (tid & 15) * 4;
    float acc[4][4] = {};

    for (int k0 = 0; k0 < C_; k0 += 16) {
        float4 av = *(const float4*)(X + (size_t)(rowBase + aRow) * C_ + k0 + aCol);
        As[aCol + 0][aRow] = av.x; As[aCol + 1][aRow] = av.y;
        As[aCol + 2][aRow] = av.z; As[aCol + 3][aRow] = av.w;
        float4 bv = *(const float4*)(W + (size_t)(k0 + bRow) * FA_ + colBase + bCol);
        *(float4*)&Bs[bRow][bCol] = bv;
        __syncthreads();
        #pragma unroll
        for (int k = 0; k < 16; k++) {
            float a[4], b[4];
            #pragma unroll
            for (int i = 0; i < 4; i++) a[i] = As[k][ty * 4 + i];
            #pragma unroll
            for (int j = 0; j < 4; j++) b[j] = Bs[k][tx * 4 + j];
            #pragma unroll
            for (int i = 0; i < 4; i++)
                #pragma unroll
                for (int j = 0; j < 4; j++) acc[i][j] = fmaf(a[i], b[j], acc[i][j]);
        }
        __syncthreads();
    }

    float ysc = powf(sqrtf((float)FA_) / log1pf((float)FA_), alpha[0]);
    #pragma unroll
    for (int i = 0; i < 4; i++) {
        int r = rowBase + ty * 4 + i;
        float xn = g_xn[r];
        int bb = r >> 10, t = r & (T_ - 1);
        #pragma unroll
        for (int j = 0; j < 4; j++) {
            int c = colBase + tx * 4 + j;
            float dot = acc[i][j];
            float dist = xn + g_wna[c] - 2.f * dot;
            float y = (dot * dot / (dist + EPSY) + bias[c]) * ysc;
            int g = c >> 6, d = c & 63;
            int h = g % 12;
            float* dst = (g < 12) ? g_q : ((g < 24) ? g_k : g_v);
            dst[(((size_t)bb * H_ + h) * T_ + t) * D_ + d] = y;
        }
    }
}

// ---------------- scores: S = yat(q,k), causal, triangular tiles only ----------------
__global__ __launch_bounds__(256) void score_kernel() {
    int bc = blockIdx.x, br = blockIdx.y;
    if (bc > br) return;                      // fully masked tile
    int bh = blockIdx.z;
    const float* Q = g_q + (size_t)bh * T_ * D_;
    const float* K = g_k + (size_t)bh * T_ * D_;
    __shared__ float Qs[64][65];
    __shared__ float Ks[64][65];
    int tid = threadIdx.x;
    int tx = tid & 15, ty = tid >> 4;
    int lrow = tid >> 4, lcol = (tid & 15) * 4;

    #pragma unroll
    for (int rr = 0; rr < 4; rr++) {
        int row = rr * 16 + lrow;
        float4 qv = *(const float4*)(Q + (size_t)(br * 64 + row) * D_ + lcol);
        Qs[row][lcol] = qv.x; Qs[row][lcol+1] = qv.y; Qs[row][lcol+2] = qv.z; Qs[row][lcol+3] = qv.w;
        float4 kv = *(const float4*)(K + (size_t)(bc * 64 + row) * D_ + lcol);
        Ks[row][lcol] = kv.x; Ks[row][lcol+1] = kv.y; Ks[row][lcol+2] = kv.z; Ks[row][lcol+3] = kv.w;
    }
    __syncthreads();

    float acc[4][4] = {};
    #pragma unroll 8
    for (int kk = 0; kk < 64; kk++) {
        float a[4], b[4];
        #pragma unroll
        for (int i = 0; i < 4; i++) a[i] = Qs[ty * 4 + i][kk];
        #pragma unroll
        for (int j = 0; j < 4; j++) b[j] = Ks[tx * 4 + j][kk];
        #pragma unroll
        for (int i = 0; i < 4; i++)
            #pragma unroll
            for (int j = 0; j < 4; j++) acc[i][j] = fmaf(a[i], b[j], acc[i][j]);
    }

    const float* qn = g_qn + bh * T_;
    const float* kn = g_kn + bh * T_;
    #pragma unroll
    for (int i = 0; i < 4; i++) {
        int gi = br * 64 + ty * 4 + i;
        float qni = qn[gi];
        #pragma unroll
        for (int j = 0; j < 4; j++) {
            int gj = bc * 64 + tx * 4 + j;
            float s = acc[i][j] * 0.125f;           // 1/sqrt(D)
            float val = (s * s) / (qni + kn[gj] - 2.f * s + EPSY);
            g_S[((size_t)bh * T_ + gi) * T_ + gj] = val;  // j>gi entries overwritten by softmax
        }
    }
}

// ---------------- row softmax over j in [0, i], zero-fill up to tile boundary ----------------
__global__ __launch_bounds__(256) void softmax_kernel() {
    __shared__ float sh[256];
    int ridx = blockIdx.x;                  // bh*T + i
    int i = ridx & (T_ - 1);
    float* p = g_S + (size_t)ridx * T_;
    int n = i + 1;
    int nz_end = ((i >> 6) + 1) << 6;       // end of diagonal 64-tile

    float v[4]; int cnt = 0;
    float m = -3.4e38f;
    for (int j = threadIdx.x; j < n; j += 256) { float x = p[j]; v[cnt++] = x; m = fmaxf(m, x); }
    sh[threadIdx.x] = m; __syncthreads();
    for (int o = 128; o; o >>= 1) { if (threadIdx.x < o) sh[threadIdx.x] = fmaxf(sh[threadIdx.x], sh[threadIdx.x + o]); __syncthreads(); }
    m = sh[0]; __syncthreads();

    float s = 0.f;
    for (int t = 0; t < cnt; t++) { float e = expf(v[t] - m); v[t] = e; s += e; }
    sh[threadIdx.x] = s; __syncthreads();
    for (int o = 128; o; o >>= 1) { if (threadIdx.x < o) sh[threadIdx.x] += sh[threadIdx.x + o]; __syncthreads(); }
    float inv = 1.f / sh[0];

    cnt = 0;
    for (int j = threadIdx.x; j < n; j += 256) p[j] = v[cnt++] * inv;
    for (int j = n + threadIdx.x; j < nz_end; j += 256) p[j] = 0.f;  // masked tail of diag tile
}

// ---------------- PV: O = S*V, triangular k loop; writes [B,T,C] layout ----------------
__global__ __launch_bounds__(256) void pv_kernel() {
    int br = blockIdx.x;          // query row tile
    int bh = blockIdx.y;
    __shared__ float Ss[64][65];
    __shared__ float Vs[64][64];
    int tid = threadIdx.x;
    int tx = tid & 15, ty = tid >> 4;
    int lrow = tid >> 4, lcol = (tid & 15) * 4;
    const float* V    = g_v + (size_t)bh * T_ * D_;
    const float* Srow = g_S + ((size_t)bh * T_ + br * 64) * T_;
    float acc[4][4] = {};

    for (int kt = 0; kt <= br; kt++) {
        #pragma unroll
        for (int rr = 0; rr < 4; rr++) {
            int row = rr * 16 + lrow;
            float4 sv = *(const float4*)(Srow + (size_t)row * T_ + kt * 64 + lcol);
            Ss[row][lcol] = sv.x; Ss[row][lcol+1] = sv.y; Ss[row][lcol+2] = sv.z; Ss[row][lcol+3] = sv.w;
            float4 vv = *(const float4*)(V + (size_t)(kt * 64 + row) * D_ + lcol);
            *(float4*)&Vs[row][lcol] = vv;
        }
        __syncthreads();
        #pragma unroll 8
        for (int kk = 0; kk < 64; kk++) {
            float a[4], b[4];
            #pragma unroll
            for (int i = 0; i < 4; i++) a[i] = Ss[ty * 4 + i][kk];
            #pragma unroll
            for (int j = 0; j < 4; j++) b[j] = Vs[kk][tx * 4 + j];
            #pragma unroll
            for (int i = 0; i < 4; i++)
                #pragma unroll
                for (int j = 0; j < 4; j++) acc[i][j] = fmaf(a[i], b[j], acc[i][j]);
        }
        __syncthreads();
    }

    int bb = bh / 12, h = bh % 12;
    #pragma unroll
    for (int i = 0; i < 4; i++) {
        int t = br * 64 + ty * 4 + i;
        #pragma unroll
        for (int j = 0; j < 4; j++)
            g_ao[(size_t)(bb * T_ + t) * C_ + h * D_ + tx * 4 + j] = acc[i][j];
    }
}

// ---------------- proj yat_dense GEMM: [4096,768] x [768,768] -> d_out ----------------
__global__ __launch_bounds__(256) void proj_kernel(const float* __restrict__ W,
                                                   const float* __restrict__ bias,
                                                   const float* __restrict__ alpha,
                                                   float* __restrict__ out) {
    __shared__ float As[16][64];
    __shared__ float Bs[16][64];
    const int tid = threadIdx.x;
    const int tx = tid & 15, ty = tid >> 4;
    const int rowBase = blockIdx.y * 64;
    const int colBase = blockIdx.x * 64;
    const int aRow = tid >> 2, aCol = (tid & 3) * 4;
    const int bRow = tid >> 4, bCol = (tid & 15) * 4;
    float acc[4][4] = {};

    for (int k0 = 0; k0 < C_; k0 += 16) {
        float4 av = *(const float4*)(g_ao + (size_t)(rowBase + aRow) * C_ + k0 + aCol);
        As[aCol + 0][aRow] = av.x; As[aCol + 1][aRow] = av.y;
        As[aCol + 2][aRow] = av.z; As[aCol + 3][aRow] = av.w;
        float4 bv = *(const float4*)(W + (size_t)(k0 + bRow) * C_ + colBase + bCol);
        *(float4*)&Bs[bRow][bCol] = bv;
        __syncthreads();
        #pragma unroll
        for (int k = 0; k < 16; k++) {
            float a[4], b[4];
            #pragma unroll
            for (int i = 0; i < 4; i++) a[i] = As[k][ty * 4 + i];
            #pragma unroll
            for (int j = 0; j < 4; j++) b[j] = Bs[k][tx * 4 + j];
            #pragma unroll
            for (int i = 0; i < 4; i++)
                #pragma unroll
                for (int j = 0; j < 4; j++) acc[i][j] = fmaf(a[i], b[j], acc[i][j]);
        }
        __syncthreads();
    }

    float ysc = powf(sqrtf((float)C_) / log1pf((float)C_), alpha[0]);
    #pragma unroll
    for (int i = 0; i < 4; i++) {
        int r = rowBase + ty * 4 + i;
        float xn = g_aon[r];
        #pragma unroll
        for (int j = 0; j < 4; j++) {
            int c = colBase + tx * 4 + j;
            float dot = acc[i][j];
            float dist = xn + g_wnp[c] - 2.f * dot;
            out[(size_t)r * C_ + c] = (dot * dot / (dist + EPSY) + bias[c]) * ysc;
        }
    }
}

// ---------------- launch ----------------
extern "C" void kernel_launch(void* const* d_in, const int* in_sizes, int n_in,
                              void* d_out, int out_size) {
    const float* x  = (const float*)d_in[0];
    // d_in[1] = causal mask (bool) — structure known, unused
    const float* Wa = (const float*)d_in[2];
    const float* ba = (const float*)d_in[3];
    const float* aa = (const float*)d_in[4];
    const float* Wp = (const float*)d_in[5];
    const float* bp = (const float*)d_in[6];
    const float* ap = (const float*)d_in[7];
    float* out = (float*)d_out;

    rownorm_x   <<<ROWS_, 256>>>(x);
    colnorm_attn<<<(FA_ + 127) / 128, 128>>>(Wa);
    qkv_kernel  <<<dim3(FA_ / 64, ROWS_ / 64), 256>>>(x, Wa, ba, aa);
    qknorm_kernel<<<(2 * BHT_) / 8, 256>>>();
    score_kernel<<<dim3(T_ / 64, T_ / 64, B_ * H_), 256>>>();
    softmax_kernel<<<BHT_, 256>>>();
    pv_kernel   <<<dim3(T_ / 64, B_ * H_), 256>>>();
    rownorm_ao  <<<ROWS_, 256>>>();
    colnorm_proj<<<(C_ + 127) / 128, 128>>>(Wp);
    proj_kernel <<<dim3(C_ / 64, ROWS_ / 64), 256>>>(Wp, bp, ap, out);
}

// round 3
// speedup vs baseline: 1.3381x; 1.3381x over previous
#include <cuda_runtime.h>
#include <math.h>

// Problem constants
#define B_   4
#define T_   1024
#define C_   768
#define H_   12
#define D_   64
#define FA_  (3*C_)          // 2304
#define BHT_ (B_*H_*T_)      // 49152
#define ROWS_ (B_*T_)        // 4096
#define EPSY (1.0f/137.0f)

// ---------------- scratch (device globals: allocation-free) ----------------
__device__ float g_q [B_*H_*T_*D_];
__device__ float g_k [B_*H_*T_*D_];
__device__ float g_v [B_*H_*T_*D_];
__device__ float g_S [(size_t)B_*H_*T_*T_];   // 201 MB score matrix
__device__ float g_ao[B_*T_*C_];              // attention output [B,T,C]
__device__ float g_xn [ROWS_];                // ||x_row||^2
__device__ float g_aon[ROWS_];                // ||ao_row||^2
__device__ float g_wna[FA_];                  // ||W_attn col||^2
__device__ float g_wnp[C_];                   // ||W_proj col||^2
__device__ float g_qn [BHT_];
__device__ float g_kn [BHT_];

// ---------------- tf32 MMA helpers ----------------
__device__ __forceinline__ unsigned f2tf32(float x) {
    unsigned r;
    asm("cvt.rna.tf32.f32 %0, %1;" : "=r"(r) : "f"(x));
    return r;
}

__device__ __forceinline__ void mma_tf32(float* d, const unsigned* a, const unsigned* b) {
    asm volatile("mma.sync.aligned.m16n8k8.row.col.f32.tf32.tf32.f32 "
        "{%0,%1,%2,%3}, {%4,%5,%6,%7}, {%8,%9}, {%0,%1,%2,%3};"
        : "+f"(d[0]), "+f"(d[1]), "+f"(d[2]), "+f"(d[3])
        : "r"(a[0]), "r"(a[1]), "r"(a[2]), "r"(a[3]), "r"(b[0]), "r"(b[1]));
}

// ---------------- norm kernels ----------------
__global__ void rownorm_x(const float* __restrict__ X) {
    __shared__ float sh[256];
    int r = blockIdx.x;
    const float* p = X + (size_t)r * C_;
    float s = 0.f;
    for (int c = threadIdx.x; c < C_; c += 256) { float v = p[c]; s += v*v; }
    sh[threadIdx.x] = s; __syncthreads();
    for (int o = 128; o; o >>= 1) { if (threadIdx.x < o) sh[threadIdx.x] += sh[threadIdx.x + o]; __syncthreads(); }
    if (threadIdx.x == 0) g_xn[r] = sh[0];
}

__global__ void rownorm_ao() {
    __shared__ float sh[256];
    int r = blockIdx.x;
    const float* p = g_ao + (size_t)r * C_;
    float s = 0.f;
    for (int c = threadIdx.x; c < C_; c += 256) { float v = p[c]; s += v*v; }
    sh[threadIdx.x] = s; __syncthreads();
    for (int o = 128; o; o >>= 1) { if (threadIdx.x < o) sh[threadIdx.x] += sh[threadIdx.x + o]; __syncthreads(); }
    if (threadIdx.x == 0) g_aon[r] = sh[0];
}

__global__ void colnorm_attn(const float* __restrict__ W) {
    int c = blockIdx.x * blockDim.x + threadIdx.x;
    if (c >= FA_) return;
    float s = 0.f;
    for (int r = 0; r < C_; r++) { float v = W[(size_t)r * FA_ + c]; s += v*v; }
    g_wna[c] = s;
}

__global__ void colnorm_proj(const float* __restrict__ W) {
    int c = blockIdx.x * blockDim.x + threadIdx.x;
    if (c >= C_) return;
    float s = 0.f;
    for (int r = 0; r < C_; r++) { float v = W[(size_t)r * C_ + c]; s += v*v; }
    g_wnp[c] = s;
}

__global__ void qknorm_kernel() {
    int gw   = (blockIdx.x * blockDim.x + threadIdx.x) >> 5;
    int lane = threadIdx.x & 31;
    if (gw >= 2 * BHT_) return;
    bool isQ = gw < BHT_;
    int r = isQ ? gw : gw - BHT_;
    const float* p = (isQ ? g_q : g_k) + (size_t)r * D_;
    float a = p[lane], b = p[lane + 32];
    float s = a*a + b*b;
    #pragma unroll
    for (int o = 16; o; o >>= 1) s += __shfl_xor_sync(0xffffffffu, s, o);
    if (lane == 0) (isQ ? g_qn : g_kn)[r] = s;
}

// ============ tf32 tensor-core yat GEMM: 128x128 block, 4 warps of 64x64 ============
// smem [k][m] / [k][n] with word-stride 136 => fragment loads conflict-free.
#define SSTR 136

__global__ __launch_bounds__(128) void qkv_tc(const float* __restrict__ X,
                                              const float* __restrict__ W,
                                              const float* __restrict__ bias,
                                              const float* __restrict__ alpha) {
    __shared__ unsigned As[32][SSTR];
    __shared__ unsigned Bs[32][SSTR];
    const int tid  = threadIdx.x;
    const int lane = tid & 31;
    const int warp = tid >> 5;
    const int g = lane >> 2, t = lane & 3;
    const int wm = (warp >> 1) * 64, wn = (warp & 1) * 64;
    const int rowBase = blockIdx.y * 128;
    const int colBase = blockIdx.x * 128;

    float acc[4][8][4];
    #pragma unroll
    for (int i = 0; i < 4; i++)
        #pragma unroll
        for (int j = 0; j < 8; j++)
            #pragma unroll
            for (int e = 0; e < 4; e++) acc[i][j][e] = 0.f;

    const int kr = tid >> 2, cb = (tid & 3) * 32;

    for (int k0 = 0; k0 < C_; k0 += 32) {
        // stage A [128m x 32k] -> As[k][m], tf32-converted
        const float* Ap = X + (size_t)(rowBase + tid) * C_ + k0;
        #pragma unroll
        for (int j = 0; j < 8; j++) {
            float4 v = *(const float4*)(Ap + j * 4);
            As[j*4+0][tid] = f2tf32(v.x);
            As[j*4+1][tid] = f2tf32(v.y);
            As[j*4+2][tid] = f2tf32(v.z);
            As[j*4+3][tid] = f2tf32(v.w);
        }
        // stage B [32k x 128n] -> Bs[k][n]
        const float* Bp = W + (size_t)(k0 + kr) * FA_ + colBase + cb;
        #pragma unroll
        for (int j = 0; j < 8; j++) {
            float4 v = *(const float4*)(Bp + j * 4);
            Bs[kr][cb + j*4 + 0] = f2tf32(v.x);
            Bs[kr][cb + j*4 + 1] = f2tf32(v.y);
            Bs[kr][cb + j*4 + 2] = f2tf32(v.z);
            Bs[kr][cb + j*4 + 3] = f2tf32(v.w);
        }
        __syncthreads();

        #pragma unroll
        for (int kk = 0; kk < 32; kk += 8) {
            unsigned a[4][4], b[8][2];
            #pragma unroll
            for (int mt = 0; mt < 4; mt++) {
                int m0 = wm + mt * 16;
                a[mt][0] = As[kk + t    ][m0 + g];
                a[mt][1] = As[kk + t    ][m0 + g + 8];
                a[mt][2] = As[kk + t + 4][m0 + g];
                a[mt][3] = As[kk + t + 4][m0 + g + 8];
            }
            #pragma unroll
            for (int nt = 0; nt < 8; nt++) {
                int n0 = wn + nt * 8;
                b[nt][0] = Bs[kk + t    ][n0 + g];
                b[nt][1] = Bs[kk + t + 4][n0 + g];
            }
            #pragma unroll
            for (int mt = 0; mt < 4; mt++)
                #pragma unroll
                for (int nt = 0; nt < 8; nt++)
                    mma_tf32(acc[mt][nt], a[mt], b[nt]);
        }
        __syncthreads();
    }

    float ysc = powf(sqrtf((float)FA_) / log1pf((float)FA_), alpha[0]);
    #pragma unroll
    for (int mt = 0; mt < 4; mt++) {
        #pragma unroll
        for (int e2 = 0; e2 < 2; e2++) {
            int r = rowBase + wm + mt * 16 + g + e2 * 8;
            float xn = g_xn[r];
            int bb = r >> 10, tt = r & (T_ - 1);
            #pragma unroll
            for (int nt = 0; nt < 8; nt++) {
                #pragma unroll
                for (int e1 = 0; e1 < 2; e1++) {
                    int c = colBase + wn + nt * 8 + t * 2 + e1;
                    float dot = acc[mt][nt][e2 * 2 + e1];
                    float dist = xn + g_wna[c] - 2.f * dot;
                    float y = (dot * dot / (dist + EPSY) + bias[c]) * ysc;
                    int gg = c >> 6, d = c & 63;
                    int h = gg % 12;
                    float* dst = (gg < 12) ? g_q : ((gg < 24) ? g_k : g_v);
                    dst[(((size_t)bb * H_ + h) * T_ + tt) * D_ + d] = y;
                }
            }
        }
    }
}

__global__ __launch_bounds__(128) void proj_tc(const float* __restrict__ W,
                                               const float* __restrict__ bias,
                                               const float* __restrict__ alpha,
                                               float* __restrict__ out) {
    __shared__ unsigned As[32][SSTR];
    __shared__ unsigned Bs[32][SSTR];
    const int tid  = threadIdx.x;
    const int lane = tid & 31;
    const int warp = tid >> 5;
    const int g = lane >> 2, t = lane & 3;
    const int wm = (warp >> 1) * 64, wn = (warp & 1) * 64;
    const int rowBase = blockIdx.y * 128;
    const int colBase = blockIdx.x * 128;

    float acc[4][8][4];
    #pragma unroll
    for (int i = 0; i < 4; i++)
        #pragma unroll
        for (int j = 0; j < 8; j++)
            #pragma unroll
            for (int e = 0; e < 4; e++) acc[i][j][e] = 0.f;

    const int kr = tid >> 2, cb = (tid & 3) * 32;

    for (int k0 = 0; k0 < C_; k0 += 32) {
        const float* Ap = g_ao + (size_t)(rowBase + tid) * C_ + k0;
        #pragma unroll
        for (int j = 0; j < 8; j++) {
            float4 v = *(const float4*)(Ap + j * 4);
            As[j*4+0][tid] = f2tf32(v.x);
            As[j*4+1][tid] = f2tf32(v.y);
            As[j*4+2][tid] = f2tf32(v.z);
            As[j*4+3][tid] = f2tf32(v.w);
        }
        const float* Bp = W + (size_t)(k0 + kr) * C_ + colBase + cb;
        #pragma unroll
        for (int j = 0; j < 8; j++) {
            float4 v = *(const float4*)(Bp + j * 4);
            Bs[kr][cb + j*4 + 0] = f2tf32(v.x);
            Bs[kr][cb + j*4 + 1] = f2tf32(v.y);
            Bs[kr][cb + j*4 + 2] = f2tf32(v.z);
            Bs[kr][cb + j*4 + 3] = f2tf32(v.w);
        }
        __syncthreads();

        #pragma unroll
        for (int kk = 0; kk < 32; kk += 8) {
            unsigned a[4][4], b[8][2];
            #pragma unroll
            for (int mt = 0; mt < 4; mt++) {
                int m0 = wm + mt * 16;
                a[mt][0] = As[kk + t    ][m0 + g];
                a[mt][1] = As[kk + t    ][m0 + g + 8];
                a[mt][2] = As[kk + t + 4][m0 + g];
                a[mt][3] = As[kk + t + 4][m0 + g + 8];
            }
            #pragma unroll
            for (int nt = 0; nt < 8; nt++) {
                int n0 = wn + nt * 8;
                b[nt][0] = Bs[kk + t    ][n0 + g];
                b[nt][1] = Bs[kk + t + 4][n0 + g];
            }
            #pragma unroll
            for (int mt = 0; mt < 4; mt++)
                #pragma unroll
                for (int nt = 0; nt < 8; nt++)
                    mma_tf32(acc[mt][nt], a[mt], b[nt]);
        }
        __syncthreads();
    }

    float ysc = powf(sqrtf((float)C_) / log1pf((float)C_), alpha[0]);
    #pragma unroll
    for (int mt = 0; mt < 4; mt++) {
        #pragma unroll
        for (int e2 = 0; e2 < 2; e2++) {
            int r = rowBase + wm + mt * 16 + g + e2 * 8;
            float xn = g_aon[r];
            #pragma unroll
            for (int nt = 0; nt < 8; nt++) {
                #pragma unroll
                for (int e1 = 0; e1 < 2; e1++) {
                    int c = colBase + wn + nt * 8 + t * 2 + e1;
                    float dot = acc[mt][nt][e2 * 2 + e1];
                    float dist = xn + g_wnp[c] - 2.f * dot;
                    out[(size_t)r * C_ + c] = (dot * dot / (dist + EPSY) + bias[c]) * ysc;
                }
            }
        }
    }
}

// ---------------- scores: S = yat(q,k), causal, triangular tiles only ----------------
__global__ __launch_bounds__(256) void score_kernel() {
    int bc = blockIdx.x, br = blockIdx.y;
    if (bc > br) return;                      // fully masked tile
    int bh = blockIdx.z;
    const float* Q = g_q + (size_t)bh * T_ * D_;
    const float* K = g_k + (size_t)bh * T_ * D_;
    __shared__ float Qs[64][65];
    __shared__ float Ks[64][65];
    int tid = threadIdx.x;
    int tx = tid & 15, ty = tid >> 4;
    int lrow = tid >> 4, lcol = (tid & 15) * 4;

    #pragma unroll
    for (int rr = 0; rr < 4; rr++) {
        int row = rr * 16 + lrow;
        float4 qv = *(const float4*)(Q + (size_t)(br * 64 + row) * D_ + lcol);
        Qs[row][lcol] = qv.x; Qs[row][lcol+1] = qv.y; Qs[row][lcol+2] = qv.z; Qs[row][lcol+3] = qv.w;
        float4 kv = *(const float4*)(K + (size_t)(bc * 64 + row) * D_ + lcol);
        Ks[row][lcol] = kv.x; Ks[row][lcol+1] = kv.y; Ks[row][lcol+2] = kv.z; Ks[row][lcol+3] = kv.w;
    }
    __syncthreads();

    float acc[4][4] = {};
    #pragma unroll 8
    for (int kk = 0; kk < 64; kk++) {
        float a[4], b[4];
        #pragma unroll
        for (int i = 0; i < 4; i++) a[i] = Qs[ty * 4 + i][kk];
        #pragma unroll
        for (int j = 0; j < 4; j++) b[j] = Ks[tx * 4 + j][kk];
        #pragma unroll
        for (int i = 0; i < 4; i++)
            #pragma unroll
            for (int j = 0; j < 4; j++) acc[i][j] = fmaf(a[i], b[j], acc[i][j]);
    }

    const float* qn = g_qn + bh * T_;
    const float* kn = g_kn + bh * T_;
    #pragma unroll
    for (int i = 0; i < 4; i++) {
        int gi = br * 64 + ty * 4 + i;
        float qni = qn[gi];
        #pragma unroll
        for (int j = 0; j < 4; j++) {
            int gj = bc * 64 + tx * 4 + j;
            float s = acc[i][j] * 0.125f;           // 1/sqrt(D)
            float val = (s * s) / (qni + kn[gj] - 2.f * s + EPSY);
            g_S[((size_t)bh * T_ + gi) * T_ + gj] = val;
        }
    }
}

// ---------------- row softmax over j in [0, i], zero-fill up to tile boundary ----------------
__global__ __launch_bounds__(256) void softmax_kernel() {
    __shared__ float sh[256];
    int ridx = blockIdx.x;                  // bh*T + i
    int i = ridx & (T_ - 1);
    float* p = g_S + (size_t)ridx * T_;
    int n = i + 1;
    int nz_end = ((i >> 6) + 1) << 6;       // end of diagonal 64-tile

    float v[4]; int cnt = 0;
    float m = -3.4e38f;
    for (int j = threadIdx.x; j < n; j += 256) { float x = p[j]; v[cnt++] = x; m = fmaxf(m, x); }
    sh[threadIdx.x] = m; __syncthreads();
    for (int o = 128; o; o >>= 1) { if (threadIdx.x < o) sh[threadIdx.x] = fmaxf(sh[threadIdx.x], sh[threadIdx.x + o]); __syncthreads(); }
    m = sh[0]; __syncthreads();

    float s = 0.f;
    for (int tt = 0; tt < cnt; tt++) { float e = expf(v[tt] - m); v[tt] = e; s += e; }
    sh[threadIdx.x] = s; __syncthreads();
    for (int o = 128; o; o >>= 1) { if (threadIdx.x < o) sh[threadIdx.x] += sh[threadIdx.x + o]; __syncthreads(); }
    float inv = 1.f / sh[0];

    cnt = 0;
    for (int j = threadIdx.x; j < n; j += 256) p[j] = v[cnt++] * inv;
    for (int j = n + threadIdx.x; j < nz_end; j += 256) p[j] = 0.f;
}

// ---------------- PV: O = S*V, triangular k loop; writes [B,T,C] layout ----------------
__global__ __launch_bounds__(256) void pv_kernel() {
    int br = blockIdx.x;          // query row tile
    int bh = blockIdx.y;
    __shared__ float Ss[64][65];
    __shared__ float Vs[64][64];
    int tid = threadIdx.x;
    int tx = tid & 15, ty = tid >> 4;
    int lrow = tid >> 4, lcol = (tid & 15) * 4;
    const float* V    = g_v + (size_t)bh * T_ * D_;
    const float* Srow = g_S + ((size_t)bh * T_ + br * 64) * T_;
    float acc[4][4] = {};

    for (int kt = 0; kt <= br; kt++) {
        #pragma unroll
        for (int rr = 0; rr < 4; rr++) {
            int row = rr * 16 + lrow;
            float4 sv = *(const float4*)(Srow + (size_t)row * T_ + kt * 64 + lcol);
            Ss[row][lcol] = sv.x; Ss[row][lcol+1] = sv.y; Ss[row][lcol+2] = sv.z; Ss[row][lcol+3] = sv.w;
            float4 vv = *(const float4*)(V + (size_t)(kt * 64 + row) * D_ + lcol);
            *(float4*)&Vs[row][lcol] = vv;
        }
        __syncthreads();
        #pragma unroll 8
        for (int kk = 0; kk < 64; kk++) {
            float a[4], b[4];
            #pragma unroll
            for (int i = 0; i < 4; i++) a[i] = Ss[ty * 4 + i][kk];
            #pragma unroll
            for (int j = 0; j < 4; j++) b[j] = Vs[kk][tx * 4 + j];
            #pragma unroll
            for (int i = 0; i < 4; i++)
                #pragma unroll
                for (int j = 0; j < 4; j++) acc[i][j] = fmaf(a[i], b[j], acc[i][j]);
        }
        __syncthreads();
    }

    int bb = bh / 12, h = bh % 12;
    #pragma unroll
    for (int i = 0; i < 4; i++) {
        int t = br * 64 + ty * 4 + i;
        #pragma unroll
        for (int j = 0; j < 4; j++)
            g_ao[(size_t)(bb * T_ + t) * C_ + h * D_ + tx * 4 + j] = acc[i][j];
    }
}

// ---------------- launch ----------------
extern "C" void kernel_launch(void* const* d_in, const int* in_sizes, int n_in,
                              void* d_out, int out_size) {
    const float* x  = (const float*)d_in[0];
    // d_in[1] = causal mask (bool) — structure known, unused
    const float* Wa = (const float*)d_in[2];
    const float* ba = (const float*)d_in[3];
    const float* aa = (const float*)d_in[4];
    const float* Wp = (const float*)d_in[5];
    const float* bp = (const float*)d_in[6];
    const float* ap = (const float*)d_in[7];
    float* out = (float*)d_out;

    rownorm_x   <<<ROWS_, 256>>>(x);
    colnorm_attn<<<(FA_ + 127) / 128, 128>>>(Wa);
    qkv_tc      <<<dim3(FA_ / 128, ROWS_ / 128), 128>>>(x, Wa, ba, aa);
    qknorm_kernel<<<(2 * BHT_) / 8, 256>>>();
    score_kernel<<<dim3(T_ / 64, T_ / 64, B_ * H_), 256>>>();
    softmax_kernel<<<BHT_, 256>>>();
    pv_kernel   <<<dim3(T_ / 64, B_ * H_), 256>>>();
    rownorm_ao  <<<ROWS_, 256>>>();
    colnorm_proj<<<(C_ + 127) / 128, 128>>>(Wp);
    proj_tc     <<<dim3(C_ / 128, ROWS_ / 128), 128>>>(Wp, bp, ap, out);
}

// round 4
// speedup vs baseline: 1.8369x; 1.3727x over previous
#include <cuda_runtime.h>
#include <math.h>

// Problem constants
#define B_   4
#define T_   1024
#define C_   768
#define H_   12
#define D_   64
#define FA_  (3*C_)          // 2304
#define BHT_ (B_*H_*T_)      // 49152
#define ROWS_ (B_*T_)        // 4096
#define EPSY (1.0f/137.0f)

// ---------------- scratch (device globals: allocation-free) ----------------
__device__ float g_q [B_*H_*T_*D_];
__device__ float g_k [B_*H_*T_*D_];
__device__ float g_v [B_*H_*T_*D_];
__device__ float g_ao[B_*T_*C_];              // attention output [B,T,C]
__device__ float g_xn [ROWS_];                // ||x_row||^2
__device__ float g_aon[ROWS_];                // ||ao_row||^2
__device__ float g_wna[FA_];                  // ||W_attn col||^2
__device__ float g_wnp[C_];                   // ||W_proj col||^2

// ---------------- tf32 MMA helpers ----------------
__device__ __forceinline__ unsigned f2tf32(float x) {
    unsigned r;
    asm("cvt.rna.tf32.f32 %0, %1;" : "=r"(r) : "f"(x));
    return r;
}

__device__ __forceinline__ void mma_tf32(float* d, const unsigned* a, const unsigned* b) {
    asm volatile("mma.sync.aligned.m16n8k8.row.col.f32.tf32.tf32.f32 "
        "{%0,%1,%2,%3}, {%4,%5,%6,%7}, {%8,%9}, {%0,%1,%2,%3};"
        : "+f"(d[0]), "+f"(d[1]), "+f"(d[2]), "+f"(d[3])
        : "r"(a[0]), "r"(a[1]), "r"(a[2]), "r"(a[3]), "r"(b[0]), "r"(b[1]));
}

// guarded exp for x <= 0: yat scores are tiny so |x| is almost always < 1/16
__device__ __forceinline__ float gexp(float x) {
    if (x > -0.0625f)
        return 1.f + x*(1.f + x*(0.5f + x*(0.16666667f + x*0.041666667f)));
    if (x < -25.f) return 0.f;
    return expf(x);
}

// ---------------- norm kernels ----------------
__global__ void rownorm_x(const float* __restrict__ X) {
    __shared__ float sh[256];
    int r = blockIdx.x;
    const float* p = X + (size_t)r * C_;
    float s = 0.f;
    for (int c = threadIdx.x; c < C_; c += 256) { float v = p[c]; s += v*v; }
    sh[threadIdx.x] = s; __syncthreads();
    for (int o = 128; o; o >>= 1) { if (threadIdx.x < o) sh[threadIdx.x] += sh[threadIdx.x + o]; __syncthreads(); }
    if (threadIdx.x == 0) g_xn[r] = sh[0];
}

__global__ void rownorm_ao() {
    __shared__ float sh[256];
    int r = blockIdx.x;
    const float* p = g_ao + (size_t)r * C_;
    float s = 0.f;
    for (int c = threadIdx.x; c < C_; c += 256) { float v = p[c]; s += v*v; }
    sh[threadIdx.x] = s; __syncthreads();
    for (int o = 128; o; o >>= 1) { if (threadIdx.x < o) sh[threadIdx.x] += sh[threadIdx.x + o]; __syncthreads(); }
    if (threadIdx.x == 0) g_aon[r] = sh[0];
}

__global__ void colnorm_attn(const float* __restrict__ W) {
    int c = blockIdx.x * blockDim.x + threadIdx.x;
    if (c >= FA_) return;
    float s = 0.f;
    for (int r = 0; r < C_; r++) { float v = W[(size_t)r * FA_ + c]; s += v*v; }
    g_wna[c] = s;
}

__global__ void colnorm_proj(const float* __restrict__ W) {
    int c = blockIdx.x * blockDim.x + threadIdx.x;
    if (c >= C_) return;
    float s = 0.f;
    for (int r = 0; r < C_; r++) { float v = W[(size_t)r * C_ + c]; s += v*v; }
    g_wnp[c] = s;
}

// ============ tf32 tensor-core yat GEMM: 128x128 block, 4 warps of 64x64 ============
#define SSTR 136

__global__ __launch_bounds__(128) void qkv_tc(const float* __restrict__ X,
                                              const float* __restrict__ W,
                                              const float* __restrict__ bias,
                                              const float* __restrict__ alpha) {
    __shared__ unsigned As[32][SSTR];
    __shared__ unsigned Bs[32][SSTR];
    const int tid  = threadIdx.x;
    const int lane = tid & 31;
    const int warp = tid >> 5;
    const int g = lane >> 2, t = lane & 3;
    const int wm = (warp >> 1) * 64, wn = (warp & 1) * 64;
    const int rowBase = blockIdx.y * 128;
    const int colBase = blockIdx.x * 128;

    float acc[4][8][4];
    #pragma unroll
    for (int i = 0; i < 4; i++)
        #pragma unroll
        for (int j = 0; j < 8; j++)
            #pragma unroll
            for (int e = 0; e < 4; e++) acc[i][j][e] = 0.f;

    const int kr = tid >> 2, cb = (tid & 3) * 32;

    for (int k0 = 0; k0 < C_; k0 += 32) {
        const float* Ap = X + (size_t)(rowBase + tid) * C_ + k0;
        #pragma unroll
        for (int j = 0; j < 8; j++) {
            float4 v = *(const float4*)(Ap + j * 4);
            As[j*4+0][tid] = f2tf32(v.x);
            As[j*4+1][tid] = f2tf32(v.y);
            As[j*4+2][tid] = f2tf32(v.z);
            As[j*4+3][tid] = f2tf32(v.w);
        }
        const float* Bp = W + (size_t)(k0 + kr) * FA_ + colBase + cb;
        #pragma unroll
        for (int j = 0; j < 8; j++) {
            float4 v = *(const float4*)(Bp + j * 4);
            Bs[kr][cb + j*4 + 0] = f2tf32(v.x);
            Bs[kr][cb + j*4 + 1] = f2tf32(v.y);
            Bs[kr][cb + j*4 + 2] = f2tf32(v.z);
            Bs[kr][cb + j*4 + 3] = f2tf32(v.w);
        }
        __syncthreads();

        #pragma unroll
        for (int kk = 0; kk < 32; kk += 8) {
            unsigned a[4][4], b[8][2];
            #pragma unroll
            for (int mt = 0; mt < 4; mt++) {
                int m0 = wm + mt * 16;
                a[mt][0] = As[kk + t    ][m0 + g];
                a[mt][1] = As[kk + t    ][m0 + g + 8];
                a[mt][2] = As[kk + t + 4][m0 + g];
                a[mt][3] = As[kk + t + 4][m0 + g + 8];
            }
            #pragma unroll
            for (int nt = 0; nt < 8; nt++) {
                int n0 = wn + nt * 8;
                b[nt][0] = Bs[kk + t    ][n0 + g];
                b[nt][1] = Bs[kk + t + 4][n0 + g];
            }
            #pragma unroll
            for (int mt = 0; mt < 4; mt++)
                #pragma unroll
                for (int nt = 0; nt < 8; nt++)
                    mma_tf32(acc[mt][nt], a[mt], b[nt]);
        }
        __syncthreads();
    }

    float ysc = powf(sqrtf((float)FA_) / log1pf((float)FA_), alpha[0]);
    #pragma unroll
    for (int mt = 0; mt < 4; mt++) {
        #pragma unroll
        for (int e2 = 0; e2 < 2; e2++) {
            int r = rowBase + wm + mt * 16 + g + e2 * 8;
            float xn = g_xn[r];
            int bb = r >> 10, tt = r & (T_ - 1);
            #pragma unroll
            for (int nt = 0; nt < 8; nt++) {
                #pragma unroll
                for (int e1 = 0; e1 < 2; e1++) {
                    int c = colBase + wn + nt * 8 + t * 2 + e1;
                    float dot = acc[mt][nt][e2 * 2 + e1];
                    float dist = xn + g_wna[c] - 2.f * dot;
                    float y = (dot * dot / (dist + EPSY) + bias[c]) * ysc;
                    int gg = c >> 6, d = c & 63;
                    int h = gg % 12;
                    float* dst = (gg < 12) ? g_q : ((gg < 24) ? g_k : g_v);
                    dst[(((size_t)bb * H_ + h) * T_ + tt) * D_ + d] = y;
                }
            }
        }
    }
}

__global__ __launch_bounds__(128) void proj_tc(const float* __restrict__ W,
                                               const float* __restrict__ bias,
                                               const float* __restrict__ alpha,
                                               float* __restrict__ out) {
    __shared__ unsigned As[32][SSTR];
    __shared__ unsigned Bs[32][SSTR];
    const int tid  = threadIdx.x;
    const int lane = tid & 31;
    const int warp = tid >> 5;
    const int g = lane >> 2, t = lane & 3;
    const int wm = (warp >> 1) * 64, wn = (warp & 1) * 64;
    const int rowBase = blockIdx.y * 128;
    const int colBase = blockIdx.x * 128;

    float acc[4][8][4];
    #pragma unroll
    for (int i = 0; i < 4; i++)
        #pragma unroll
        for (int j = 0; j < 8; j++)
            #pragma unroll
            for (int e = 0; e < 4; e++) acc[i][j][e] = 0.f;

    const int kr = tid >> 2, cb = (tid & 3) * 32;

    for (int k0 = 0; k0 < C_; k0 += 32) {
        const float* Ap = g_ao + (size_t)(rowBase + tid) * C_ + k0;
        #pragma unroll
        for (int j = 0; j < 8; j++) {
            float4 v = *(const float4*)(Ap + j * 4);
            As[j*4+0][tid] = f2tf32(v.x);
            As[j*4+1][tid] = f2tf32(v.y);
            As[j*4+2][tid] = f2tf32(v.z);
            As[j*4+3][tid] = f2tf32(v.w);
        }
        const float* Bp = W + (size_t)(k0 + kr) * C_ + colBase + cb;
        #pragma unroll
        for (int j = 0; j < 8; j++) {
            float4 v = *(const float4*)(Bp + j * 4);
            Bs[kr][cb + j*4 + 0] = f2tf32(v.x);
            Bs[kr][cb + j*4 + 1] = f2tf32(v.y);
            Bs[kr][cb + j*4 + 2] = f2tf32(v.z);
            Bs[kr][cb + j*4 + 3] = f2tf32(v.w);
        }
        __syncthreads();

        #pragma unroll
        for (int kk = 0; kk < 32; kk += 8) {
            unsigned a[4][4], b[8][2];
            #pragma unroll
            for (int mt = 0; mt < 4; mt++) {
                int m0 = wm + mt * 16;
                a[mt][0] = As[kk + t    ][m0 + g];
                a[mt][1] = As[kk + t    ][m0 + g + 8];
                a[mt][2] = As[kk + t + 4][m0 + g];
                a[mt][3] = As[kk + t + 4][m0 + g + 8];
            }
            #pragma unroll
            for (int nt = 0; nt < 8; nt++) {
                int n0 = wn + nt * 8;
                b[nt][0] = Bs[kk + t    ][n0 + g];
                b[nt][1] = Bs[kk + t + 4][n0 + g];
            }
            #pragma unroll
            for (int mt = 0; mt < 4; mt++)
                #pragma unroll
                for (int nt = 0; nt < 8; nt++)
                    mma_tf32(acc[mt][nt], a[mt], b[nt]);
        }
        __syncthreads();
    }

    float ysc = powf(sqrtf((float)C_) / log1pf((float)C_), alpha[0]);
    #pragma unroll
    for (int mt = 0; mt < 4; mt++) {
        #pragma unroll
        for (int e2 = 0; e2 < 2; e2++) {
            int r = rowBase + wm + mt * 16 + g + e2 * 8;
            float xn = g_aon[r];
            #pragma unroll
            for (int nt = 0; nt < 8; nt++) {
                #pragma unroll
                for (int e1 = 0; e1 < 2; e1++) {
                    int c = colBase + wn + nt * 8 + t * 2 + e1;
                    float dot = acc[mt][nt][e2 * 2 + e1];
                    float dist = xn + g_wnp[c] - 2.f * dot;
                    out[(size_t)r * C_ + c] = (dot * dot / (dist + EPSY) + bias[c]) * ysc;
                }
            }
        }
    }
}

// ============ fused yat attention: score + online softmax + PV ============
// One block = 64 q rows of one head. 4 warps x 16 rows. tf32 MMA both GEMMs.
#define FSTR 68

__global__ __launch_bounds__(128) void attn_fused() {
    const int br = (int)gridDim.x - 1 - (int)blockIdx.x;   // big tiles first
    const int bh = blockIdx.y;
    const float* Qg = g_q + ((size_t)bh * T_ + br * 64) * D_;
    const float* Kg = g_k + (size_t)bh * T_ * D_;
    const float* Vg = g_v + (size_t)bh * T_ * D_;

    __shared__ unsigned QP[64 * FSTR];   // Q tf32, then P tf32
    __shared__ unsigned KV[64 * FSTR];   // K tile, then V tile
    __shared__ float qn_s[64], kn_s[64];

    const int tid = threadIdx.x, lane = tid & 31, warp = tid >> 5;
    const int g = lane >> 2, t = lane & 3;
    const int wq = warp * 16;

    // ---- stage Q (tf32) + row norms (fp32) ----
    {
        int row = tid >> 1, half = tid & 1;
        const float* p = Qg + row * D_ + half * 32;
        float s = 0.f;
        #pragma unroll
        for (int j = 0; j < 8; j++) {
            float4 v = *(const float4*)(p + j * 4);
            s += v.x*v.x + v.y*v.y + v.z*v.z + v.w*v.w;
            unsigned* d = &QP[row * FSTR + half * 32 + j * 4];
            d[0] = f2tf32(v.x); d[1] = f2tf32(v.y); d[2] = f2tf32(v.z); d[3] = f2tf32(v.w);
        }
        s += __shfl_xor_sync(0xffffffffu, s, 1);
        if (half == 0) qn_s[row] = s;
    }
    __syncthreads();

    // ---- Q fragments to registers (held whole kernel) ----
    unsigned qa[8][4];
    #pragma unroll
    for (int kk8 = 0; kk8 < 8; kk8++) {
        int kk = kk8 * 8;
        qa[kk8][0] = QP[(wq + g    ) * FSTR + kk + t];
        qa[kk8][1] = QP[(wq + g + 8) * FSTR + kk + t];
        qa[kk8][2] = QP[(wq + g    ) * FSTR + kk + t + 4];
        qa[kk8][3] = QP[(wq + g + 8) * FSTR + kk + t + 4];
    }
    const float qn0 = qn_s[wq + g], qn1 = qn_s[wq + g + 8];
    __syncthreads();

    float O[8][4];
    #pragma unroll
    for (int i = 0; i < 8; i++)
        #pragma unroll
        for (int e = 0; e < 4; e++) O[i][e] = 0.f;
    float m0 = -1e30f, m1 = -1e30f, l0 = 0.f, l1 = 0.f;

    const int gi0 = br * 64 + wq + g;
    const int gi1 = gi0 + 8;

    for (int kt = 0; kt <= br; kt++) {
        // ---- stage K tile + col norms ----
        {
            int row = tid >> 1, half = tid & 1;
            const float* p = Kg + (size_t)(kt * 64 + row) * D_ + half * 32;
            float s = 0.f;
            #pragma unroll
            for (int j = 0; j < 8; j++) {
                float4 v = *(const float4*)(p + j * 4);
                s += v.x*v.x + v.y*v.y + v.z*v.z + v.w*v.w;
                unsigned* d = &KV[row * FSTR + half * 32 + j * 4];
                d[0] = f2tf32(v.x); d[1] = f2tf32(v.y); d[2] = f2tf32(v.z); d[3] = f2tf32(v.w);
            }
            s += __shfl_xor_sync(0xffffffffu, s, 1);
            if (half == 0) kn_s[row] = s;
        }
        __syncthreads();

        // ---- S = Q K^T (16x64 per warp) ----
        float acc[8][4];
        #pragma unroll
        for (int i = 0; i < 8; i++)
            #pragma unroll
            for (int e = 0; e < 4; e++) acc[i][e] = 0.f;
        #pragma unroll
        for (int kk8 = 0; kk8 < 8; kk8++) {
            #pragma unroll
            for (int nt = 0; nt < 8; nt++) {
                unsigned b[2];
                b[0] = KV[(nt * 8 + g) * FSTR + kk8 * 8 + t];
                b[1] = KV[(nt * 8 + g) * FSTR + kk8 * 8 + t + 4];
                mma_tf32(acc[nt], qa[kk8], b);
            }
        }

        // ---- yat transform + causal mask ----
        float tmax0 = -1e30f, tmax1 = -1e30f;
        #pragma unroll
        for (int nt = 0; nt < 8; nt++) {
            int lc = nt * 8 + 2 * t;
            int j0 = kt * 64 + lc;
            float kna = kn_s[lc], knb = kn_s[lc + 1];
            float s00 = acc[nt][0] * 0.125f, s01 = acc[nt][1] * 0.125f;
            float s10 = acc[nt][2] * 0.125f, s11 = acc[nt][3] * 0.125f;
            float v00 = (s00 * s00) / (qn0 + kna - 2.f * s00 + EPSY);
            float v01 = (s01 * s01) / (qn0 + knb - 2.f * s01 + EPSY);
            float v10 = (s10 * s10) / (qn1 + kna - 2.f * s10 + EPSY);
            float v11 = (s11 * s11) / (qn1 + knb - 2.f * s11 + EPSY);
            if (kt == br) {
                if (j0     > gi0) v00 = -1e30f;
                if (j0 + 1 > gi0) v01 = -1e30f;
                if (j0     > gi1) v10 = -1e30f;
                if (j0 + 1 > gi1) v11 = -1e30f;
            }
            acc[nt][0] = v00; acc[nt][1] = v01; acc[nt][2] = v10; acc[nt][3] = v11;
            tmax0 = fmaxf(tmax0, fmaxf(v00, v01));
            tmax1 = fmaxf(tmax1, fmaxf(v10, v11));
        }
        tmax0 = fmaxf(tmax0, __shfl_xor_sync(0xffffffffu, tmax0, 1));
        tmax0 = fmaxf(tmax0, __shfl_xor_sync(0xffffffffu, tmax0, 2));
        tmax1 = fmaxf(tmax1, __shfl_xor_sync(0xffffffffu, tmax1, 1));
        tmax1 = fmaxf(tmax1, __shfl_xor_sync(0xffffffffu, tmax1, 2));

        float mn0 = fmaxf(m0, tmax0), mn1 = fmaxf(m1, tmax1);
        float f0 = gexp(m0 - mn0), f1 = gexp(m1 - mn1);
        m0 = mn0; m1 = mn1;

        // ---- P = exp(val - m), write to smem as tf32, accumulate sums ----
        float sum0 = 0.f, sum1 = 0.f;
        #pragma unroll
        for (int nt = 0; nt < 8; nt++) {
            int lc = nt * 8 + 2 * t;
            float p00 = gexp(acc[nt][0] - mn0);
            float p01 = gexp(acc[nt][1] - mn0);
            float p10 = gexp(acc[nt][2] - mn1);
            float p11 = gexp(acc[nt][3] - mn1);
            sum0 += p00 + p01; sum1 += p10 + p11;
            QP[(wq + g    ) * FSTR + lc    ] = f2tf32(p00);
            QP[(wq + g    ) * FSTR + lc + 1] = f2tf32(p01);
            QP[(wq + g + 8) * FSTR + lc    ] = f2tf32(p10);
            QP[(wq + g + 8) * FSTR + lc + 1] = f2tf32(p11);
        }
        sum0 += __shfl_xor_sync(0xffffffffu, sum0, 1);
        sum0 += __shfl_xor_sync(0xffffffffu, sum0, 2);
        sum1 += __shfl_xor_sync(0xffffffffu, sum1, 1);
        sum1 += __shfl_xor_sync(0xffffffffu, sum1, 2);
        l0 = l0 * f0 + sum0;
        l1 = l1 * f1 + sum1;

        // rescale O accumulators
        #pragma unroll
        for (int nt = 0; nt < 8; nt++) {
            O[nt][0] *= f0; O[nt][1] *= f0;
            O[nt][2] *= f1; O[nt][3] *= f1;
        }
        __syncthreads();   // all warps done reading K

        // ---- stage V tile into KV ----
        {
            int row = tid >> 1, half = tid & 1;
            const float* p = Vg + (size_t)(kt * 64 + row) * D_ + half * 32;
            #pragma unroll
            for (int j = 0; j < 8; j++) {
                float4 v = *(const float4*)(p + j * 4);
                unsigned* d = &KV[row * FSTR + half * 32 + j * 4];
                d[0] = f2tf32(v.x); d[1] = f2tf32(v.y); d[2] = f2tf32(v.z); d[3] = f2tf32(v.w);
            }
        }
        __syncthreads();

        // ---- O += P V ----
        #pragma unroll
        for (int kk8 = 0; kk8 < 8; kk8++) {
            unsigned a[4];
            a[0] = QP[(wq + g    ) * FSTR + kk8 * 8 + t];
            a[1] = QP[(wq + g + 8) * FSTR + kk8 * 8 + t];
            a[2] = QP[(wq + g    ) * FSTR + kk8 * 8 + t + 4];
            a[3] = QP[(wq + g + 8) * FSTR + kk8 * 8 + t + 4];
            #pragma unroll
            for (int nt = 0; nt < 8; nt++) {
                unsigned b[2];
                b[0] = KV[(kk8 * 8 + t    ) * FSTR + nt * 8 + g];
                b[1] = KV[(kk8 * 8 + t + 4) * FSTR + nt * 8 + g];
                mma_tf32(O[nt], a, b);
            }
        }
        __syncthreads();   // before next K staging overwrites KV
    }

    // ---- epilogue: normalize, write [B,T,C] ----
    float inv0 = 1.f / l0, inv1 = 1.f / l1;
    int bb = bh / H_, h = bh % H_;
    size_t row0 = (size_t)bb * T_ + br * 64 + wq + g;
    float* ao0 = g_ao + row0 * C_ + h * D_;
    float* ao1 = ao0 + 8 * C_;
    #pragma unroll
    for (int nt = 0; nt < 8; nt++) {
        int lc = nt * 8 + 2 * t;
        float2 w0 = make_float2(O[nt][0] * inv0, O[nt][1] * inv0);
        float2 w1 = make_float2(O[nt][2] * inv1, O[nt][3] * inv1);
        *(float2*)(ao0 + lc) = w0;
        *(float2*)(ao1 + lc) = w1;
    }
}

// ---------------- launch ----------------
extern "C" void kernel_launch(void* const* d_in, const int* in_sizes, int n_in,
                              void* d_out, int out_size) {
    const float* x  = (const float*)d_in[0];
    // d_in[1] = causal mask (bool) — structure known, unused
    const float* Wa = (const float*)d_in[2];
    const float* ba = (const float*)d_in[3];
    const float* aa = (const float*)d_in[4];
    const float* Wp = (const float*)d_in[5];
    const float* bp = (const float*)d_in[6];
    const float* ap = (const float*)d_in[7];
    float* out = (float*)d_out;

    rownorm_x   <<<ROWS_, 256>>>(x);
    colnorm_attn<<<(FA_ + 127) / 128, 128>>>(Wa);
    qkv_tc      <<<dim3(FA_ / 128, ROWS_ / 128), 128>>>(x, Wa, ba, aa);
    attn_fused  <<<dim3(T_ / 64, B_ * H_), 128>>>();
    rownorm_ao  <<<ROWS_, 256>>>();
    colnorm_proj<<<(C_ + 127) / 128, 128>>>(Wp);
    proj_tc     <<<dim3(C_ / 128, ROWS_ / 128), 128>>>(Wp, bp, ap, out);
}

// round 5
// speedup vs baseline: 2.0881x; 1.1367x over previous
#include <cuda_runtime.h>
#include <math.h>

// Problem constants
#define B_   4
#define T_   1024
#define C_   768
#define H_   12
#define D_   64
#define FA_  (3*C_)          // 2304
#define BHT_ (B_*H_*T_)      // 49152
#define ROWS_ (B_*T_)        // 4096
#define EPSY (1.0f/137.0f)

// ---------------- scratch (device globals: allocation-free) ----------------
__device__ float g_q [B_*H_*T_*D_];           // tf32-rounded
__device__ float g_k [B_*H_*T_*D_];           // tf32-rounded
__device__ float g_v [B_*H_*T_*D_];           // tf32-rounded
__device__ float g_ao[B_*T_*C_];              // attention output, tf32-rounded
__device__ float g_xt [ROWS_*C_];             // x, tf32-rounded
__device__ float g_wat[C_*FA_];               // W_attn, tf32-rounded
__device__ float g_wpt[C_*C_];                // W_proj, tf32-rounded
__device__ float g_xn [ROWS_];
__device__ float g_aon[ROWS_];
__device__ float g_wna[FA_];
__device__ float g_wnp[C_];
__device__ float g_qn [BHT_];
__device__ float g_kn [BHT_];

// ---------------- helpers ----------------
__device__ __forceinline__ unsigned f2tf32(float x) {
    unsigned r;
    asm("cvt.rna.tf32.f32 %0, %1;" : "=r"(r) : "f"(x));
    return r;
}

__device__ __forceinline__ void mma_tf32(float* d, const unsigned* a, const unsigned* b) {
    asm volatile("mma.sync.aligned.m16n8k8.row.col.f32.tf32.tf32.f32 "
        "{%0,%1,%2,%3}, {%4,%5,%6,%7}, {%8,%9}, {%0,%1,%2,%3};"
        : "+f"(d[0]), "+f"(d[1]), "+f"(d[2]), "+f"(d[3])
        : "r"(a[0]), "r"(a[1]), "r"(a[2]), "r"(a[3]), "r"(b[0]), "r"(b[1]));
}

__device__ __forceinline__ void cp16(void* smem, const void* gmem) {
    unsigned s = (unsigned)__cvta_generic_to_shared(smem);
    asm volatile("cp.async.cg.shared.global [%0], [%1], 16;" :: "r"(s), "l"(gmem));
}
#define CP_COMMIT() asm volatile("cp.async.commit_group;")
#define CP_WAIT(N)  asm volatile("cp.async.wait_group %0;" :: "n"(N))

// guarded exp for x <= 0: yat scores are tiny so |x| is almost always < 1/16
__device__ __forceinline__ float gexp(float x) {
    if (x > -0.0625f)
        return 1.f + x*(1.f + x*(0.5f + x*(0.16666667f + x*0.041666667f)));
    if (x < -25.f) return 0.f;
    return expf(x);
}

// ---------------- tf32 pre-rounding ----------------
__global__ void round_tf32(const float* __restrict__ in, float* __restrict__ out, int n4) {
    int i = blockIdx.x * blockDim.x + threadIdx.x;
    if (i >= n4) return;
    float4 v = ((const float4*)in)[i];
    v.x = __uint_as_float(f2tf32(v.x));
    v.y = __uint_as_float(f2tf32(v.y));
    v.z = __uint_as_float(f2tf32(v.z));
    v.w = __uint_as_float(f2tf32(v.w));
    ((float4*)out)[i] = v;
}

// ---------------- norm kernels (exact fp32 inputs) ----------------
__global__ void rownorm_x(const float* __restrict__ X) {
    __shared__ float sh[256];
    int r = blockIdx.x;
    const float* p = X + (size_t)r * C_;
    float s = 0.f;
    for (int c = threadIdx.x; c < C_; c += 256) { float v = p[c]; s += v*v; }
    sh[threadIdx.x] = s; __syncthreads();
    for (int o = 128; o; o >>= 1) { if (threadIdx.x < o) sh[threadIdx.x] += sh[threadIdx.x + o]; __syncthreads(); }
    if (threadIdx.x == 0) g_xn[r] = sh[0];
}

__global__ void rownorm_ao() {
    __shared__ float sh[256];
    int r = blockIdx.x;
    const float* p = g_ao + (size_t)r * C_;
    float s = 0.f;
    for (int c = threadIdx.x; c < C_; c += 256) { float v = p[c]; s += v*v; }
    sh[threadIdx.x] = s; __syncthreads();
    for (int o = 128; o; o >>= 1) { if (threadIdx.x < o) sh[threadIdx.x] += sh[threadIdx.x + o]; __syncthreads(); }
    if (threadIdx.x == 0) g_aon[r] = sh[0];
}

__global__ void colnorm_attn(const float* __restrict__ W) {
    int c = blockIdx.x * blockDim.x + threadIdx.x;
    if (c >= FA_) return;
    float s = 0.f;
    for (int r = 0; r < C_; r++) { float v = W[(size_t)r * FA_ + c]; s += v*v; }
    g_wna[c] = s;
}

__global__ void colnorm_proj(const float* __restrict__ W) {
    int c = blockIdx.x * blockDim.x + threadIdx.x;
    if (c >= C_) return;
    float s = 0.f;
    for (int r = 0; r < C_; r++) { float v = W[(size_t)r * C_ + c]; s += v*v; }
    g_wnp[c] = s;
}

__global__ void qknorm_kernel() {
    int gw   = (blockIdx.x * blockDim.x + threadIdx.x) >> 5;
    int lane = threadIdx.x & 31;
    if (gw >= 2 * BHT_) return;
    bool isQ = gw < BHT_;
    int r = isQ ? gw : gw - BHT_;
    const float* p = (isQ ? g_q : g_k) + (size_t)r * D_;
    float a = p[lane], b = p[lane + 32];
    float s = a*a + b*b;
    #pragma unroll
    for (int o = 16; o; o >>= 1) s += __shfl_xor_sync(0xffffffffu, s, o);
    if (lane == 0) (isQ ? g_qn : g_kn)[r] = s;
}

// ============ tf32 yat GEMM, cp.async double-buffered ============
// A staged [m][k] stride 36 (bank 4g+t distinct); B staged [k][n] stride 136 (8t+g distinct).
#define AST 36
#define BST 136
#define GEMM_SMEM ((2*128*AST + 2*32*BST)*4)

template<int LDN>
__device__ __forceinline__ void gemm_body(const float* __restrict__ Asrc,
                                          const float* __restrict__ Bsrc,
                                          float acc[4][8][4],
                                          int rowBase, int colBase) {
    extern __shared__ float smf[];
    float* Asf[2] = { smf, smf + 128*AST };
    float* Bsf[2] = { smf + 2*128*AST, smf + 2*128*AST + 32*BST };
    const int tid  = threadIdx.x;
    const int lane = tid & 31;
    const int warp = tid >> 5;
    const int g = lane >> 2, t = lane & 3;
    const int wm = (warp >> 1) * 64, wn = (warp & 1) * 64;
    const int brow = tid >> 2, bcol = (tid & 3) * 32;
    const int NIT = C_ / 32;

    // stage 0
    {
        const float* Ap = Asrc + (size_t)(rowBase + tid) * C_;
        #pragma unroll
        for (int j = 0; j < 8; j++) cp16(&Asf[0][tid*AST + j*4], Ap + j*4);
        const float* Bp = Bsrc + (size_t)brow * LDN + colBase + bcol;
        #pragma unroll
        for (int j = 0; j < 8; j++) cp16(&Bsf[0][brow*BST + bcol + j*4], Bp + j*4);
        CP_COMMIT();
    }

    for (int it = 0; it < NIT; it++) {
        CP_WAIT(0);
        __syncthreads();
        if (it + 1 < NIT) {
            int s = (it + 1) & 1, k0 = (it + 1) * 32;
            const float* Ap = Asrc + (size_t)(rowBase + tid) * C_ + k0;
            #pragma unroll
            for (int j = 0; j < 8; j++) cp16(&Asf[s][tid*AST + j*4], Ap + j*4);
            const float* Bp = Bsrc + (size_t)(k0 + brow) * LDN + colBase + bcol;
            #pragma unroll
            for (int j = 0; j < 8; j++) cp16(&Bsf[s][brow*BST + bcol + j*4], Bp + j*4);
            CP_COMMIT();
        }
        const float* Af = Asf[it & 1];
        const float* Bf = Bsf[it & 1];
        #pragma unroll
        for (int kk8 = 0; kk8 < 4; kk8++) {
            int kk = kk8 * 8;
            unsigned a[4][4], b[8][2];
            #pragma unroll
            for (int mt = 0; mt < 4; mt++) {
                int m0 = wm + mt * 16;
                a[mt][0] = __float_as_uint(Af[(m0 + g    ) * AST + kk + t]);
                a[mt][1] = __float_as_uint(Af[(m0 + g + 8) * AST + kk + t]);
                a[mt][2] = __float_as_uint(Af[(m0 + g    ) * AST + kk + t + 4]);
                a[mt][3] = __float_as_uint(Af[(m0 + g + 8) * AST + kk + t + 4]);
            }
            #pragma unroll
            for (int nt = 0; nt < 8; nt++) {
                int n0 = wn + nt * 8;
                b[nt][0] = __float_as_uint(Bf[(kk + t    ) * BST + n0 + g]);
                b[nt][1] = __float_as_uint(Bf[(kk + t + 4) * BST + n0 + g]);
            }
            #pragma unroll
            for (int mt = 0; mt < 4; mt++)
                #pragma unroll
                for (int nt = 0; nt < 8; nt++)
                    mma_tf32(acc[mt][nt], a[mt], b[nt]);
        }
        __syncthreads();
    }
}

__global__ __launch_bounds__(128) void qkv_tc(const float* __restrict__ bias,
                                              const float* __restrict__ alpha) {
    const int rowBase = blockIdx.y * 128;
    const int colBase = blockIdx.x * 128;
    float acc[4][8][4];
    #pragma unroll
    for (int i = 0; i < 4; i++)
        #pragma unroll
        for (int j = 0; j < 8; j++)
            #pragma unroll
            for (int e = 0; e < 4; e++) acc[i][j][e] = 0.f;

    gemm_body<FA_>(g_xt, g_wat, acc, rowBase, colBase);

    const int lane = threadIdx.x & 31, warp = threadIdx.x >> 5;
    const int g = lane >> 2, t = lane & 3;
    const int wm = (warp >> 1) * 64, wn = (warp & 1) * 64;
    float ysc = powf(sqrtf((float)FA_) / log1pf((float)FA_), alpha[0]);
    #pragma unroll
    for (int mt = 0; mt < 4; mt++) {
        #pragma unroll
        for (int e2 = 0; e2 < 2; e2++) {
            int r = rowBase + wm + mt * 16 + g + e2 * 8;
            float xn = g_xn[r];
            int bb = r >> 10, tt = r & (T_ - 1);
            #pragma unroll
            for (int nt = 0; nt < 8; nt++) {
                #pragma unroll
                for (int e1 = 0; e1 < 2; e1++) {
                    int c = colBase + wn + nt * 8 + t * 2 + e1;
                    float dot = acc[mt][nt][e2 * 2 + e1];
                    float dist = xn + g_wna[c] - 2.f * dot;
                    float y = (dot * dot / (dist + EPSY) + bias[c]) * ysc;
                    int gg = c >> 6, d = c & 63;
                    int h = gg % 12;
                    float* dst = (gg < 12) ? g_q : ((gg < 24) ? g_k : g_v);
                    dst[(((size_t)bb * H_ + h) * T_ + tt) * D_ + d] = __uint_as_float(f2tf32(y));
                }
            }
        }
    }
}

__global__ __launch_bounds__(128) void proj_tc(const float* __restrict__ bias,
                                               const float* __restrict__ alpha,
                                               float* __restrict__ out) {
    const int rowBase = blockIdx.y * 128;
    const int colBase = blockIdx.x * 128;
    float acc[4][8][4];
    #pragma unroll
    for (int i = 0; i < 4; i++)
        #pragma unroll
        for (int j = 0; j < 8; j++)
            #pragma unroll
            for (int e = 0; e < 4; e++) acc[i][j][e] = 0.f;

    gemm_body<C_>(g_ao, g_wpt, acc, rowBase, colBase);

    const int lane = threadIdx.x & 31, warp = threadIdx.x >> 5;
    const int g = lane >> 2, t = lane & 3;
    const int wm = (warp >> 1) * 64, wn = (warp & 1) * 64;
    float ysc = powf(sqrtf((float)C_) / log1pf((float)C_), alpha[0]);
    #pragma unroll
    for (int mt = 0; mt < 4; mt++) {
        #pragma unroll
        for (int e2 = 0; e2 < 2; e2++) {
            int r = rowBase + wm + mt * 16 + g + e2 * 8;
            float xn = g_aon[r];
            #pragma unroll
            for (int nt = 0; nt < 8; nt++) {
                #pragma unroll
                for (int e1 = 0; e1 < 2; e1++) {
                    int c = colBase + wn + nt * 8 + t * 2 + e1;
                    float dot = acc[mt][nt][e2 * 2 + e1];
                    float dist = xn + g_wnp[c] - 2.f * dot;
                    out[(size_t)r * C_ + c] = (dot * dot / (dist + EPSY) + bias[c]) * ysc;
                }
            }
        }
    }
}

// ============ fused yat attention, cp.async pipelined ============
#define FSTR 68
#define ATTN_SMEM ((3*64*FSTR + 64)*4)

__global__ __launch_bounds__(128) void attn_fused() {
    const int br = (int)gridDim.x - 1 - (int)blockIdx.x;   // big tiles first
    const int bh = blockIdx.y;
    const float* Qg = g_q + ((size_t)bh * T_ + br * 64) * D_;
    const float* Kg = g_k + (size_t)bh * T_ * D_;
    const float* Vg = g_v + (size_t)bh * T_ * D_;
    const float* kng = g_kn + bh * T_;

    extern __shared__ unsigned ash[];
    unsigned* Ps = ash;                 // P (and initially Q)
    unsigned* Ks = ash + 64 * FSTR;
    unsigned* Vs = ash + 2 * 64 * FSTR;
    float*   knf = (float*)(ash + 3 * 64 * FSTR);

    const int tid = threadIdx.x, lane = tid & 31, warp = tid >> 5;
    const int g = lane >> 2, t = lane & 3;
    const int wq = warp * 16;
    const int srow = tid >> 1, shalf = tid & 1;
    const size_t soff = (size_t)srow * D_ + shalf * 32;
    unsigned* const sdst = (unsigned*)0 + srow * FSTR + shalf * 32; // offset pattern

    // ---- prologue: stage Q, K0+kn0, V0 ----
    {
        const float* p = Qg + soff;
        #pragma unroll
        for (int j = 0; j < 8; j++) cp16(&Ps[srow*FSTR + shalf*32 + j*4], p + j*4);
        CP_COMMIT();                                        // GQ
        const float* pk = Kg + soff;
        #pragma unroll
        for (int j = 0; j < 8; j++) cp16(&Ks[srow*FSTR + shalf*32 + j*4], pk + j*4);
        if (tid < 16) cp16(&knf[tid*4], kng + tid*4);
        CP_COMMIT();                                        // GK0
        const float* pv = Vg + soff;
        #pragma unroll
        for (int j = 0; j < 8; j++) cp16(&Vs[srow*FSTR + shalf*32 + j*4], pv + j*4);
        CP_COMMIT();                                        // GV0
    }
    CP_WAIT(2);            // Q done (warp-local rows)
    __syncwarp();

    unsigned qa[8][4];
    #pragma unroll
    for (int kk8 = 0; kk8 < 8; kk8++) {
        int kk = kk8 * 8;
        qa[kk8][0] = Ps[(wq + g    ) * FSTR + kk + t];
        qa[kk8][1] = Ps[(wq + g + 8) * FSTR + kk + t];
        qa[kk8][2] = Ps[(wq + g    ) * FSTR + kk + t + 4];
        qa[kk8][3] = Ps[(wq + g + 8) * FSTR + kk + t + 4];
    }
    const float qn0 = g_qn[bh * T_ + br * 64 + wq + g];
    const float qn1 = g_qn[bh * T_ + br * 64 + wq + g + 8];

    float O[8][4];
    #pragma unroll
    for (int i = 0; i < 8; i++)
        #pragma unroll
        for (int e = 0; e < 4; e++) O[i][e] = 0.f;
    float m0 = -1e30f, m1 = -1e30f, l0 = 0.f, l1 = 0.f;

    const int gi0 = br * 64 + wq + g;
    const int gi1 = gi0 + 8;

    for (int kt = 0; kt <= br; kt++) {
        CP_WAIT(1);          // K(kt)+kn done; V(kt) may be in flight
        __syncthreads();     // K/kn visible to all

        // ---- S = Q K^T ----
        float acc[8][4];
        #pragma unroll
        for (int i = 0; i < 8; i++)
            #pragma unroll
            for (int e = 0; e < 4; e++) acc[i][e] = 0.f;
        #pragma unroll
        for (int kk8 = 0; kk8 < 8; kk8++) {
            #pragma unroll
            for (int nt = 0; nt < 8; nt++) {
                unsigned b[2];
                b[0] = Ks[(nt * 8 + g) * FSTR + kk8 * 8 + t];
                b[1] = Ks[(nt * 8 + g) * FSTR + kk8 * 8 + t + 4];
                mma_tf32(acc[nt], qa[kk8], b);
            }
        }

        // ---- yat + causal mask ----
        float tmax0 = -1e30f, tmax1 = -1e30f;
        #pragma unroll
        for (int nt = 0; nt < 8; nt++) {
            int lc = nt * 8 + 2 * t;
            int j0 = kt * 64 + lc;
            float kna = knf[lc], knb = knf[lc + 1];
            float s00 = acc[nt][0] * 0.125f, s01 = acc[nt][1] * 0.125f;
            float s10 = acc[nt][2] * 0.125f, s11 = acc[nt][3] * 0.125f;
            float v00 = (s00 * s00) / (qn0 + kna - 2.f * s00 + EPSY);
            float v01 = (s01 * s01) / (qn0 + knb - 2.f * s01 + EPSY);
            float v10 = (s10 * s10) / (qn1 + kna - 2.f * s10 + EPSY);
            float v11 = (s11 * s11) / (qn1 + knb - 2.f * s11 + EPSY);
            if (kt == br) {
                if (j0     > gi0) v00 = -1e30f;
                if (j0 + 1 > gi0) v01 = -1e30f;
                if (j0     > gi1) v10 = -1e30f;
                if (j0 + 1 > gi1) v11 = -1e30f;
            }
            acc[nt][0] = v00; acc[nt][1] = v01; acc[nt][2] = v10; acc[nt][3] = v11;
            tmax0 = fmaxf(tmax0, fmaxf(v00, v01));
            tmax1 = fmaxf(tmax1, fmaxf(v10, v11));
        }
        tmax0 = fmaxf(tmax0, __shfl_xor_sync(0xffffffffu, tmax0, 1));
        tmax0 = fmaxf(tmax0, __shfl_xor_sync(0xffffffffu, tmax0, 2));
        tmax1 = fmaxf(tmax1, __shfl_xor_sync(0xffffffffu, tmax1, 1));
        tmax1 = fmaxf(tmax1, __shfl_xor_sync(0xffffffffu, tmax1, 2));

        float mn0 = fmaxf(m0, tmax0), mn1 = fmaxf(m1, tmax1);
        float f0 = gexp(m0 - mn0), f1 = gexp(m1 - mn1);
        m0 = mn0; m1 = mn1;

        // ---- P = exp(val - m) -> smem tf32, row sums ----
        float sum0 = 0.f, sum1 = 0.f;
        #pragma unroll
        for (int nt = 0; nt < 8; nt++) {
            int lc = nt * 8 + 2 * t;
            float p00 = gexp(acc[nt][0] - mn0);
            float p01 = gexp(acc[nt][1] - mn0);
            float p10 = gexp(acc[nt][2] - mn1);
            float p11 = gexp(acc[nt][3] - mn1);
            sum0 += p00 + p01; sum1 += p10 + p11;
            Ps[(wq + g    ) * FSTR + lc    ] = f2tf32(p00);
            Ps[(wq + g    ) * FSTR + lc + 1] = f2tf32(p01);
            Ps[(wq + g + 8) * FSTR + lc    ] = f2tf32(p10);
            Ps[(wq + g + 8) * FSTR + lc + 1] = f2tf32(p11);
        }
        sum0 += __shfl_xor_sync(0xffffffffu, sum0, 1);
        sum0 += __shfl_xor_sync(0xffffffffu, sum0, 2);
        sum1 += __shfl_xor_sync(0xffffffffu, sum1, 1);
        sum1 += __shfl_xor_sync(0xffffffffu, sum1, 2);
        l0 = l0 * f0 + sum0;
        l1 = l1 * f1 + sum1;
        #pragma unroll
        for (int nt = 0; nt < 8; nt++) {
            O[nt][0] *= f0; O[nt][1] *= f0;
            O[nt][2] *= f1; O[nt][3] *= f1;
        }

        CP_WAIT(0);          // V(kt) done (own parts)
        __syncthreads();     // V visible; all warps done reading Ks

        if (kt < br) {       // prefetch K(kt+1): overlaps PV MMA
            const float* pk = Kg + (size_t)(kt + 1) * 64 * D_ + soff;
            #pragma unroll
            for (int j = 0; j < 8; j++) cp16(&Ks[srow*FSTR + shalf*32 + j*4], pk + j*4);
            if (tid < 16) cp16(&knf[tid*4], kng + (kt + 1) * 64 + tid*4);
            CP_COMMIT();
        }

        // ---- O += P V ----
        #pragma unroll
        for (int kk8 = 0; kk8 < 8; kk8++) {
            unsigned a[4];
            a[0] = Ps[(wq + g    ) * FSTR + kk8 * 8 + t];
            a[1] = Ps[(wq + g + 8) * FSTR + kk8 * 8 + t];
            a[2] = Ps[(wq + g    ) * FSTR + kk8 * 8 + t + 4];
            a[3] = Ps[(wq + g + 8) * FSTR + kk8 * 8 + t + 4];
            #pragma unroll
            for (int nt = 0; nt < 8; nt++) {
                unsigned b[2];
                b[0] = Vs[(kk8 * 8 + t    ) * FSTR + nt * 8 + g];
                b[1] = Vs[(kk8 * 8 + t + 4) * FSTR + nt * 8 + g];
                mma_tf32(O[nt], a, b);
            }
        }
        __syncthreads();     // all warps done reading Vs

        if (kt < br) {       // prefetch V(kt+1): overlaps next S phase
            const float* pv = Vg + (size_t)(kt + 1) * 64 * D_ + soff;
            #pragma unroll
            for (int j = 0; j < 8; j++) cp16(&Vs[srow*FSTR + shalf*32 + j*4], pv + j*4);
            CP_COMMIT();
        }
    }

    // ---- epilogue: normalize, tf32-round, write [B,T,C] ----
    float inv0 = 1.f / l0, inv1 = 1.f / l1;
    int bb = bh / H_, h = bh % H_;
    size_t row0 = (size_t)bb * T_ + br * 64 + wq + g;
    float* ao0 = g_ao + row0 * C_ + h * D_;
    float* ao1 = ao0 + 8 * C_;
    #pragma unroll
    for (int nt = 0; nt < 8; nt++) {
        int lc = nt * 8 + 2 * t;
        float2 w0, w1;
        w0.x = __uint_as_float(f2tf32(O[nt][0] * inv0));
        w0.y = __uint_as_float(f2tf32(O[nt][1] * inv0));
        w1.x = __uint_as_float(f2tf32(O[nt][2] * inv1));
        w1.y = __uint_as_float(f2tf32(O[nt][3] * inv1));
        *(float2*)(ao0 + lc) = w0;
        *(float2*)(ao1 + lc) = w1;
    }
}

// ---------------- launch ----------------
extern "C" void kernel_launch(void* const* d_in, const int* in_sizes, int n_in,
                              void* d_out, int out_size) {
    const float* x  = (const float*)d_in[0];
    // d_in[1] = causal mask (bool) — structure known, unused
    const float* Wa = (const float*)d_in[2];
    const float* ba = (const float*)d_in[3];
    const float* aa = (const float*)d_in[4];
    const float* Wp = (const float*)d_in[5];
    const float* bp = (const float*)d_in[6];
    const float* ap = (const float*)d_in[7];
    float* out = (float*)d_out;

    static int attr_done = 0;
    if (!attr_done) {
        cudaFuncSetAttribute(qkv_tc,    cudaFuncAttributeMaxDynamicSharedMemorySize, GEMM_SMEM);
        cudaFuncSetAttribute(proj_tc,   cudaFuncAttributeMaxDynamicSharedMemorySize, GEMM_SMEM);
        cudaFuncSetAttribute(attn_fused,cudaFuncAttributeMaxDynamicSharedMemorySize, ATTN_SMEM);
        attr_done = 1;
    }

    float* xt;  cudaGetSymbolAddress((void**)&xt,  g_xt);
    float* wat; cudaGetSymbolAddress((void**)&wat, g_wat);
    float* wpt; cudaGetSymbolAddress((void**)&wpt, g_wpt);

    round_tf32  <<<(ROWS_*C_/4 + 255)/256, 256>>>(x,  xt,  ROWS_*C_/4);
    round_tf32  <<<(C_*FA_/4   + 255)/256, 256>>>(Wa, wat, C_*FA_/4);
    round_tf32  <<<(C_*C_/4    + 255)/256, 256>>>(Wp, wpt, C_*C_/4);
    rownorm_x   <<<ROWS_, 256>>>(x);
    colnorm_attn<<<(FA_ + 127) / 128, 128>>>(Wa);
    qkv_tc      <<<dim3(FA_ / 128, ROWS_ / 128), 128, GEMM_SMEM>>>(ba, aa);
    qknorm_kernel<<<(2 * BHT_) / 8, 256>>>();
    attn_fused  <<<dim3(T_ / 64, B_ * H_), 128, ATTN_SMEM>>>();
    rownorm_ao  <<<ROWS_, 256>>>();
    colnorm_proj<<<(C_ + 127) / 128, 128>>>(Wp);
    proj_tc     <<<dim3(C_ / 128, ROWS_ / 128), 128, GEMM_SMEM>>>(bp, ap, out);
}

// round 7
// speedup vs baseline: 2.5527x; 1.2225x over previous
#include <cuda_runtime.h>
#include <math.h>

// Problem constants
#define B_   4
#define T_   1024
#define C_   768
#define H_   12
#define D_   64
#define FA_  (3*C_)          // 2304
#define BHT_ (B_*H_*T_)      // 49152
#define ROWS_ (B_*T_)        // 4096
#define EPSY (1.0f/137.0f)

// ---------------- scratch (device globals: allocation-free) ----------------
__device__ float g_q [B_*H_*T_*D_];           // tf32-rounded
__device__ float g_k [B_*H_*T_*D_];           // tf32-rounded
__device__ float g_v [B_*H_*T_*D_];           // tf32-rounded
__device__ float g_ao[B_*T_*C_];              // attention output, tf32-rounded
__device__ float g_xt [ROWS_*C_];             // x, tf32-rounded
__device__ float g_wat[C_*FA_];               // W_attn, tf32-rounded
__device__ float g_wpt[C_*C_];                // W_proj, tf32-rounded
__device__ float g_xn [ROWS_];
__device__ float g_aon[ROWS_];
__device__ float g_aop[ROWS_*H_];             // per-head partial ||ao||^2
__device__ float g_wna[FA_];
__device__ float g_wnp[C_];
__device__ float g_qn [BHT_];
__device__ float g_kn [BHT_];

// ---------------- helpers ----------------
__device__ __forceinline__ unsigned f2tf32(float x) {
    unsigned r;
    asm("cvt.rna.tf32.f32 %0, %1;" : "=r"(r) : "f"(x));
    return r;
}

__device__ __forceinline__ void mma_tf32(float* d, const unsigned* a, const unsigned* b) {
    asm volatile("mma.sync.aligned.m16n8k8.row.col.f32.tf32.tf32.f32 "
        "{%0,%1,%2,%3}, {%4,%5,%6,%7}, {%8,%9}, {%0,%1,%2,%3};"
        : "+f"(d[0]), "+f"(d[1]), "+f"(d[2]), "+f"(d[3])
        : "r"(a[0]), "r"(a[1]), "r"(a[2]), "r"(a[3]), "r"(b[0]), "r"(b[1]));
}

__device__ __forceinline__ void cp16(void* smem, const void* gmem) {
    unsigned s = (unsigned)__cvta_generic_to_shared(smem);
    asm volatile("cp.async.cg.shared.global [%0], [%1], 16;" :: "r"(s), "l"(gmem));
}
#define CP_COMMIT() asm volatile("cp.async.commit_group;")
#define CP_WAIT(N)  asm volatile("cp.async.wait_group %0;" :: "n"(N))

// guarded exp for x <= 0: yat scores are tiny so |x| is almost always < 1/16
__device__ __forceinline__ float gexp(float x) {
    if (x > -0.0625f)
        return 1.f + x*(1.f + x*(0.5f + x*(0.16666667f + x*0.041666667f)));
    if (x < -25.f) return 0.f;
    return expf(x);
}

// ---------------- rounding / norm kernels ----------------
// x: round to tf32 AND compute exact row norms. One block per row.
__global__ __launch_bounds__(256) void round_x_norm(const float* __restrict__ in) {
    __shared__ float sh[256];
    int r = blockIdx.x;
    const float4* src = (const float4*)(in + (size_t)r * C_);
    float4* dst = (float4*)(g_xt + (size_t)r * C_);
    float s = 0.f;
    if (threadIdx.x < C_/4) {
        float4 v = src[threadIdx.x];
        s = v.x*v.x + v.y*v.y + v.z*v.z + v.w*v.w;
        v.x = __uint_as_float(f2tf32(v.x));
        v.y = __uint_as_float(f2tf32(v.y));
        v.z = __uint_as_float(f2tf32(v.z));
        v.w = __uint_as_float(f2tf32(v.w));
        dst[threadIdx.x] = v;
    }
    sh[threadIdx.x] = s; __syncthreads();
    for (int o = 128; o; o >>= 1) { if (threadIdx.x < o) sh[threadIdx.x] += sh[threadIdx.x + o]; __syncthreads(); }
    if (threadIdx.x == 0) g_xn[r] = sh[0];
}

__global__ void round_tf32(const float* __restrict__ in, float* __restrict__ out, int n4) {
    int i = blockIdx.x * blockDim.x + threadIdx.x;
    if (i >= n4) return;
    float4 v = ((const float4*)in)[i];
    v.x = __uint_as_float(f2tf32(v.x));
    v.y = __uint_as_float(f2tf32(v.y));
    v.z = __uint_as_float(f2tf32(v.z));
    v.w = __uint_as_float(f2tf32(v.w));
    ((float4*)out)[i] = v;
}

// column norms: block = 32 cols x 8 row-strips
__global__ __launch_bounds__(256) void colnorm_split(const float* __restrict__ W,
                                                     float* __restrict__ out, int ncols) {
    __shared__ float sh[8][32];
    int tx = threadIdx.x & 31, ty = threadIdx.x >> 5;
    int c = blockIdx.x * 32 + tx;
    float s = 0.f;
    for (int r = ty; r < C_; r += 8) { float v = W[(size_t)r * ncols + c]; s += v*v; }
    sh[ty][tx] = s; __syncthreads();
    if (ty == 0) {
        float t = 0.f;
        #pragma unroll
        for (int i = 0; i < 8; i++) t += sh[i][tx];
        out[c] = t;
    }
}

// sum per-head ao norm partials
__global__ void aon_sum() {
    int r = blockIdx.x * 256 + threadIdx.x;
    if (r >= ROWS_) return;
    float s = 0.f;
    #pragma unroll
    for (int h = 0; h < H_; h++) s += g_aop[(size_t)r * H_ + h];
    g_aon[r] = s;
}

// ============ tf32 yat GEMM: 128x128 tile, 8 warps of 32x64, cp.async 2-stage ============
#define AST 36
#define BST 136
#define GEMM_SMEM ((2*128*AST + 2*32*BST)*4)

template<int LDN>
__device__ __forceinline__ void gemm_body(const float* __restrict__ Asrc,
                                          const float* __restrict__ Bsrc,
                                          float acc[2][8][4],
                                          int rowBase, int colBase) {
    extern __shared__ float smf[];
    float* Asf[2] = { smf, smf + 128*AST };
    float* Bsf[2] = { smf + 2*128*AST, smf + 2*128*AST + 32*BST };
    const int tid  = threadIdx.x;
    const int lane = tid & 31;
    const int warp = tid >> 5;
    const int g = lane >> 2, t = lane & 3;
    const int wm = (warp & 3) * 32, wn = (warp >> 2) * 64;
    const int arow = tid >> 1, ahalf = (tid & 1) * 16;
    const int brow = tid >> 3, bseg = (tid & 7) * 16;
    const int NIT = C_ / 32;

    {
        const float* Ap = Asrc + (size_t)(rowBase + arow) * C_ + ahalf;
        #pragma unroll
        for (int j = 0; j < 4; j++) cp16(&Asf[0][arow*AST + ahalf + j*4], Ap + j*4);
        const float* Bp = Bsrc + (size_t)brow * LDN + colBase + bseg;
        #pragma unroll
        for (int j = 0; j < 4; j++) cp16(&Bsf[0][brow*BST + bseg + j*4], Bp + j*4);
        CP_COMMIT();
    }

    for (int it = 0; it < NIT; it++) {
        CP_WAIT(0);
        __syncthreads();
        if (it + 1 < NIT) {
            int s = (it + 1) & 1, k0 = (it + 1) * 32;
            const float* Ap = Asrc + (size_t)(rowBase + arow) * C_ + k0 + ahalf;
            #pragma unroll
            for (int j = 0; j < 4; j++) cp16(&Asf[s][arow*AST + ahalf + j*4], Ap + j*4);
            const float* Bp = Bsrc + (size_t)(k0 + brow) * LDN + colBase + bseg;
            #pragma unroll
            for (int j = 0; j < 4; j++) cp16(&Bsf[s][brow*BST + bseg + j*4], Bp + j*4);
            CP_COMMIT();
        }
        const float* Af = Asf[it & 1];
        const float* Bf = Bsf[it & 1];
        #pragma unroll
        for (int kk8 = 0; kk8 < 4; kk8++) {
            int kk = kk8 * 8;
            unsigned a[2][4], b[8][2];
            #pragma unroll
            for (int mt = 0; mt < 2; mt++) {
                int m0 = wm + mt * 16;
                a[mt][0] = __float_as_uint(Af[(m0 + g    ) * AST + kk + t]);
                a[mt][1] = __float_as_uint(Af[(m0 + g + 8) * AST + kk + t]);
                a[mt][2] = __float_as_uint(Af[(m0 + g    ) * AST + kk + t + 4]);
                a[mt][3] = __float_as_uint(Af[(m0 + g + 8) * AST + kk + t + 4]);
            }
            #pragma unroll
            for (int nt = 0; nt < 8; nt++) {
                int n0 = wn + nt * 8;
                b[nt][0] = __float_as_uint(Bf[(kk + t    ) * BST + n0 + g]);
                b[nt][1] = __float_as_uint(Bf[(kk + t + 4) * BST + n0 + g]);
            }
            #pragma unroll
            for (int mt = 0; mt < 2; mt++)
                #pragma unroll
                for (int nt = 0; nt < 8; nt++)
                    mma_tf32(acc[mt][nt], a[mt], b[nt]);
        }
        __syncthreads();
    }
}

__global__ __launch_bounds__(256) void qkv_tc(const float* __restrict__ bias,
                                              const float* __restrict__ alpha) {
    const int rowBase = blockIdx.y * 128;
    const int colBase = blockIdx.x * 128;
    float acc[2][8][4];
    #pragma unroll
    for (int i = 0; i < 2; i++)
        #pragma unroll
        for (int j = 0; j < 8; j++)
            #pragma unroll
            for (int e = 0; e < 4; e++) acc[i][j][e] = 0.f;

    gemm_body<FA_>(g_xt, g_wat, acc, rowBase, colBase);

    const int lane = threadIdx.x & 31, warp = threadIdx.x >> 5;
    const int g = lane >> 2, t = lane & 3;
    const int wm = (warp & 3) * 32, wn = (warp >> 2) * 64;
    const int gg = (colBase + wn) >> 6;          // warp-uniform head group
    const int h = gg % 12;
    float* dst = (gg < 12) ? g_q : ((gg < 24) ? g_k : g_v);
    float ysc = powf(sqrtf((float)FA_) / log1pf((float)FA_), alpha[0]);

    #pragma unroll
    for (int mt = 0; mt < 2; mt++) {
        #pragma unroll
        for (int e2 = 0; e2 < 2; e2++) {
            int r = rowBase + wm + mt * 16 + g + e2 * 8;
            float xn = g_xn[r];
            int bb = r >> 10, tt = r & (T_ - 1);
            float ns = 0.f;
            float* drow = dst + (((size_t)bb * H_ + h) * T_ + tt) * D_;
            #pragma unroll
            for (int nt = 0; nt < 8; nt++) {
                #pragma unroll
                for (int e1 = 0; e1 < 2; e1++) {
                    int c = colBase + wn + nt * 8 + t * 2 + e1;
                    float dot = acc[mt][nt][e2 * 2 + e1];
                    float dist = xn + g_wna[c] - 2.f * dot;
                    float y = (__fdividef(dot * dot, dist + EPSY) + bias[c]) * ysc;
                    float yr = __uint_as_float(f2tf32(y));
                    drow[c & 63] = yr;
                    ns += yr * yr;
                }
            }
            if (gg < 24) {
                ns += __shfl_xor_sync(0xffffffffu, ns, 1);
                ns += __shfl_xor_sync(0xffffffffu, ns, 2);
                if (t == 0) {
                    float* np = (gg < 12) ? g_qn : g_kn;
                    np[((size_t)bb * H_ + h) * T_ + tt] = ns;
                }
            }
        }
    }
}

__global__ __launch_bounds__(256) void proj_tc(const float* __restrict__ bias,
                                               const float* __restrict__ alpha,
                                               float* __restrict__ out) {
    const int rowBase = blockIdx.y * 128;
    const int colBase = blockIdx.x * 128;
    float acc[2][8][4];
    #pragma unroll
    for (int i = 0; i < 2; i++)
        #pragma unroll
        for (int j = 0; j < 8; j++)
            #pragma unroll
            for (int e = 0; e < 4; e++) acc[i][j][e] = 0.f;

    gemm_body<C_>(g_ao, g_wpt, acc, rowBase, colBase);

    const int lane = threadIdx.x & 31, warp = threadIdx.x >> 5;
    const int g = lane >> 2, t = lane & 3;
    const int wm = (warp & 3) * 32, wn = (warp >> 2) * 64;
    float ysc = powf(sqrtf((float)C_) / log1pf((float)C_), alpha[0]);
    #pragma unroll
    for (int mt = 0; mt < 2; mt++) {
        #pragma unroll
        for (int e2 = 0; e2 < 2; e2++) {
            int r = rowBase + wm + mt * 16 + g + e2 * 8;
            float xn = g_aon[r];
            #pragma unroll
            for (int nt = 0; nt < 8; nt++) {
                #pragma unroll
                for (int e1 = 0; e1 < 2; e1++) {
                    int c = colBase + wn + nt * 8 + t * 2 + e1;
                    float dot = acc[mt][nt][e2 * 2 + e1];
                    float dist = xn + g_wnp[c] - 2.f * dot;
                    out[(size_t)r * C_ + c] = (__fdividef(dot * dot, dist + EPSY) + bias[c]) * ysc;
                }
            }
        }
    }
}

// ============ fused yat attention: 128 q-rows/block, 8 warps, cp.async pipelined ============
#define FSTR 72
#define ATTN_SMEM ((128*FSTR + 2*64*FSTR + 64)*4)

__global__ __launch_bounds__(256) void attn_fused() {
    const int br = (int)gridDim.x - 1 - (int)blockIdx.x;   // big tiles first
    const int bh = blockIdx.y;
    const float* Qg = g_q + ((size_t)bh * T_ + br * 128) * D_;
    const float* Kg = g_k + (size_t)bh * T_ * D_;
    const float* Vg = g_v + (size_t)bh * T_ * D_;
    const float* kng = g_kn + bh * T_;

    extern __shared__ unsigned ash[];
    unsigned* Ps = ash;                      // Q then P (128 rows)
    unsigned* Ks = ash + 128 * FSTR;
    unsigned* Vs = Ks + 64 * FSTR;
    float*   knf = (float*)(Vs + 64 * FSTR);

    const int tid = threadIdx.x, lane = tid & 31, warp = tid >> 5;
    const int g = lane >> 2, t = lane & 3;
    const int wq = warp * 16;
    const int qrow = tid >> 1, qhalf = (tid & 1) * 32;     // Q staging: 128 rows
    const int krow = tid >> 2, kseg = (tid & 3) * 16;      // K/V staging: 64 rows

    // ---- prologue: stage Q, K0+kn0, V0 ----
    {
        const float* p = Qg + (size_t)qrow * D_ + qhalf;
        #pragma unroll
        for (int j = 0; j < 8; j++) cp16(&Ps[qrow*FSTR + qhalf + j*4], p + j*4);
        CP_COMMIT();                                        // GQ
        const float* pk = Kg + (size_t)krow * D_ + kseg;
        #pragma unroll
        for (int j = 0; j < 4; j++) cp16(&Ks[krow*FSTR + kseg + j*4], pk + j*4);
        if (tid < 16) cp16(&knf[tid*4], kng + tid*4);
        CP_COMMIT();                                        // GK0
        const float* pv = Vg + (size_t)krow * D_ + kseg;
        #pragma unroll
        for (int j = 0; j < 4; j++) cp16(&Vs[krow*FSTR + kseg + j*4], pv + j*4);
        CP_COMMIT();                                        // GV0
    }
    CP_WAIT(2);            // Q done; warp staged exactly its own 16 rows
    __syncwarp();

    unsigned qa[8][4];
    #pragma unroll
    for (int kk8 = 0; kk8 < 8; kk8++) {
        int kk = kk8 * 8;
        qa[kk8][0] = Ps[(wq + g    ) * FSTR + kk + t];
        qa[kk8][1] = Ps[(wq + g + 8) * FSTR + kk + t];
        qa[kk8][2] = Ps[(wq + g    ) * FSTR + kk + t + 4];
        qa[kk8][3] = Ps[(wq + g + 8) * FSTR + kk + t + 4];
    }
    const float qn0 = g_qn[bh * T_ + br * 128 + wq + g];
    const float qn1 = g_qn[bh * T_ + br * 128 + wq + g + 8];

    float O[8][4];
    #pragma unroll
    for (int i = 0; i < 8; i++)
        #pragma unroll
        for (int e = 0; e < 4; e++) O[i][e] = 0.f;
    float m0 = -1e30f, m1 = -1e30f, l0 = 0.f, l1 = 0.f;

    const int gi0 = br * 128 + wq + g;
    const int gi1 = gi0 + 8;
    const int KT = 2 * br + 1;

    for (int kt = 0; kt <= KT; kt++) {
        CP_WAIT(1);          // K(kt)+kn done; V(kt) may be in flight
        __syncthreads();

        // ---- S = Q K^T ----
        float acc[8][4];
        #pragma unroll
        for (int i = 0; i < 8; i++)
            #pragma unroll
            for (int e = 0; e < 4; e++) acc[i][e] = 0.f;
        #pragma unroll
        for (int kk8 = 0; kk8 < 8; kk8++) {
            #pragma unroll
            for (int nt = 0; nt < 8; nt++) {
                unsigned b[2];
                b[0] = Ks[(nt * 8 + g) * FSTR + kk8 * 8 + t];
                b[1] = Ks[(nt * 8 + g) * FSTR + kk8 * 8 + t + 4];
                mma_tf32(acc[nt], qa[kk8], b);
            }
        }

        // ---- yat + causal mask ----
        const bool dz = ((kt << 6) + 63) > (br * 128 + wq);   // warp-uniform diag zone
        float tmax0 = -1e30f, tmax1 = -1e30f;
        #pragma unroll
        for (int nt = 0; nt < 8; nt++) {
            int lc = nt * 8 + 2 * t;
            int j0 = (kt << 6) + lc;
            float kna = knf[lc], knb = knf[lc + 1];
            float s00 = acc[nt][0] * 0.125f, s01 = acc[nt][1] * 0.125f;
            float s10 = acc[nt][2] * 0.125f, s11 = acc[nt][3] * 0.125f;
            float v00 = __fdividef(s00 * s00, qn0 + kna - 2.f * s00 + EPSY);
            float v01 = __fdividef(s01 * s01, qn0 + knb - 2.f * s01 + EPSY);
            float v10 = __fdividef(s10 * s10, qn1 + kna - 2.f * s10 + EPSY);
            float v11 = __fdividef(s11 * s11, qn1 + knb - 2.f * s11 + EPSY);
            if (dz) {
                if (j0     > gi0) v00 = -1e30f;
                if (j0 + 1 > gi0) v01 = -1e30f;
                if (j0     > gi1) v10 = -1e30f;
                if (j0 + 1 > gi1) v11 = -1e30f;
            }
            acc[nt][0] = v00; acc[nt][1] = v01; acc[nt][2] = v10; acc[nt][3] = v11;
            tmax0 = fmaxf(tmax0, fmaxf(v00, v01));
            tmax1 = fmaxf(tmax1, fmaxf(v10, v11));
        }
        tmax0 = fmaxf(tmax0, __shfl_xor_sync(0xffffffffu, tmax0, 1));
        tmax0 = fmaxf(tmax0, __shfl_xor_sync(0xffffffffu, tmax0, 2));
        tmax1 = fmaxf(tmax1, __shfl_xor_sync(0xffffffffu, tmax1, 1));
        tmax1 = fmaxf(tmax1, __shfl_xor_sync(0xffffffffu, tmax1, 2));

        float mn0 = fmaxf(m0, tmax0), mn1 = fmaxf(m1, tmax1);
        float f0 = gexp(m0 - mn0), f1 = gexp(m1 - mn1);
        m0 = mn0; m1 = mn1;

        // ---- P = exp(val - m) -> smem tf32, row sums ----
        float sum0 = 0.f, sum1 = 0.f;
        #pragma unroll
        for (int nt = 0; nt < 8; nt++) {
            int lc = nt * 8 + 2 * t;
            float p00 = gexp(acc[nt][0] - mn0);
            float p01 = gexp(acc[nt][1] - mn0);
            float p10 = gexp(acc[nt][2] - mn1);
            float p11 = gexp(acc[nt][3] - mn1);
            sum0 += p00 + p01; sum1 += p10 + p11;
            Ps[(wq + g    ) * FSTR + lc    ] = f2tf32(p00);
            Ps[(wq + g    ) * FSTR + lc + 1] = f2tf32(p01);
            Ps[(wq + g + 8) * FSTR + lc    ] = f2tf32(p10);
            Ps[(wq + g + 8) * FSTR + lc + 1] = f2tf32(p11);
        }
        sum0 += __shfl_xor_sync(0xffffffffu, sum0, 1);
        sum0 += __shfl_xor_sync(0xffffffffu, sum0, 2);
        sum1 += __shfl_xor_sync(0xffffffffu, sum1, 1);
        sum1 += __shfl_xor_sync(0xffffffffu, sum1, 2);
        l0 = l0 * f0 + sum0;
        l1 = l1 * f1 + sum1;
        #pragma unroll
        for (int nt = 0; nt < 8; nt++) {
            O[nt][0] *= f0; O[nt][1] *= f0;
            O[nt][2] *= f1; O[nt][3] *= f1;
        }

        CP_WAIT(0);          // V(kt) done
        __syncthreads();     // V visible; all warps done reading Ks

        if (kt < KT) {       // prefetch K(kt+1): overlaps PV MMA
            const float* pk = Kg + (size_t)(kt + 1) * 64 * D_ + (size_t)krow * D_ + kseg;
            #pragma unroll
            for (int j = 0; j < 4; j++) cp16(&Ks[krow*FSTR + kseg + j*4], pk + j*4);
            if (tid < 16) cp16(&knf[tid*4], kng + (kt + 1) * 64 + tid*4);
            CP_COMMIT();
        }

        // ---- O += P V ----
        #pragma unroll
        for (int kk8 = 0; kk8 < 8; kk8++) {
            unsigned a[4];
            a[0] = Ps[(wq + g    ) * FSTR + kk8 * 8 + t];
            a[1] = Ps[(wq + g + 8) * FSTR + kk8 * 8 + t];
            a[2] = Ps[(wq + g    ) * FSTR + kk8 * 8 + t + 4];
            a[3] = Ps[(wq + g + 8) * FSTR + kk8 * 8 + t + 4];
            #pragma unroll
            for (int nt = 0; nt < 8; nt++) {
                unsigned b[2];
                b[0] = Vs[(kk8 * 8 + t    ) * FSTR + nt * 8 + g];
                b[1] = Vs[(kk8 * 8 + t + 4) * FSTR + nt * 8 + g];
                mma_tf32(O[nt], a, b);
            }
        }
        __syncthreads();     // all warps done reading Vs

        if (kt < KT) {       // prefetch V(kt+1): overlaps next S phase
            const float* pv = Vg + (size_t)(kt + 1) * 64 * D_ + (size_t)krow * D_ + kseg;
            #pragma unroll
            for (int j = 0; j < 4; j++) cp16(&Vs[krow*FSTR + kseg + j*4], pv + j*4);
            CP_COMMIT();
        }
    }

    // ---- epilogue: normalize, tf32-round, write [B,T,C], per-head norm partials ----
    float inv0 = __fdividef(1.f, l0), inv1 = __fdividef(1.f, l1);
    int bb = bh / H_, h = bh % H_;
    size_t rr0 = (size_t)bb * T_ + br * 128 + wq + g;
    size_t rr1 = rr0 + 8;
    float* ao0 = g_ao + rr0 * C_ + h * D_;
    float* ao1 = g_ao + rr1 * C_ + h * D_;
    float n0 = 0.f, n1 = 0.f;
    #pragma unroll
    for (int nt = 0; nt < 8; nt++) {
        int lc = nt * 8 + 2 * t;
        float2 w0, w1;
        w0.x = __uint_as_float(f2tf32(O[nt][0] * inv0));
        w0.y = __uint_as_float(f2tf32(O[nt][1] * inv0));
        w1.x = __uint_as_float(f2tf32(O[nt][2] * inv1));
        w1.y = __uint_as_float(f2tf32(O[nt][3] * inv1));
        n0 += w0.x*w0.x + w0.y*w0.y;
        n1 += w1.x*w1.x + w1.y*w1.y;
        *(float2*)(ao0 + lc) = w0;
        *(float2*)(ao1 + lc) = w1;
    }
    n0 += __shfl_xor_sync(0xffffffffu, n0, 1);
    n0 += __shfl_xor_sync(0xffffffffu, n0, 2);
    n1 += __shfl_xor_sync(0xffffffffu, n1, 1);
    n1 += __shfl_xor_sync(0xffffffffu, n1, 2);
    if (t == 0) {
        g_aop[rr0 * H_ + h] = n0;
        g_aop[rr1 * H_ + h] = n1;
    }
}

// ---------------- launch ----------------
extern "C" void kernel_launch(void* const* d_in, const int* in_sizes, int n_in,
                              void* d_out, int out_size) {
    const float* x  = (const float*)d_in[0];
    // d_in[1] = causal mask (bool) — structure known, unused
    const float* Wa = (const float*)d_in[2];
    const float* ba = (const float*)d_in[3];
    const float* aa = (const float*)d_in[4];
    const float* Wp = (const float*)d_in[5];
    const float* bp = (const float*)d_in[6];
    const float* ap = (const float*)d_in[7];
    float* out = (float*)d_out;

    static int attr_done = 0;
    if (!attr_done) {
        cudaFuncSetAttribute(qkv_tc,     cudaFuncAttributeMaxDynamicSharedMemorySize, GEMM_SMEM);
        cudaFuncSetAttribute(proj_tc,    cudaFuncAttributeMaxDynamicSharedMemorySize, GEMM_SMEM);
        cudaFuncSetAttribute(attn_fused, cudaFuncAttributeMaxDynamicSharedMemorySize, ATTN_SMEM);
        attr_done = 1;
    }

    float* wat; cudaGetSymbolAddress((void**)&wat, g_wat);
    float* wpt; cudaGetSymbolAddress((void**)&wpt, g_wpt);
    float* wna; cudaGetSymbolAddress((void**)&wna, g_wna);
    float* wnp; cudaGetSymbolAddress((void**)&wnp, g_wnp);

    round_x_norm<<<ROWS_, 256>>>(x);
    round_tf32  <<<(C_*FA_/4 + 255)/256, 256>>>(Wa, wat, C_*FA_/4);
    round_tf32  <<<(C_*C_/4  + 255)/256, 256>>>(Wp, wpt, C_*C_/4);
    colnorm_split<<<FA_/32, 256>>>(Wa, wna, FA_);
    colnorm_split<<<C_/32,  256>>>(Wp, wnp, C_);
    qkv_tc      <<<dim3(FA_/128, ROWS_/128), 256, GEMM_SMEM>>>(ba, aa);
    attn_fused  <<<dim3(T_/128, B_*H_), 256, ATTN_SMEM>>>();
    aon_sum     <<<ROWS_/256, 256>>>();
    proj_tc     <<<dim3(C_/128, ROWS_/128), 256, GEMM_SMEM>>>(bp, ap, out);
}